// round 1
// baseline (speedup 1.0000x reference)
#include <cuda_runtime.h>
#include <math.h>

// ---------------- problem constants ----------------
constexpr int kB   = 8;
constexpr int kT   = 1024;
constexpr int kC   = 768;
constexpr int kH   = 12;
constexpr int kDH  = 64;
constexpr int kHID = 1536;   // 2*C
constexpr int kM   = 16;
constexpr int kP   = 4;
constexpr int kPRE = kM + kP;      // 20
constexpr int kTA  = kT + kPRE;    // 1044
constexpr float kLR = 0.01f, kMU = 0.9f, kDECAY = 0.001f;

// output tuple offsets (flattened concatenation, reference return order)
constexpr long OUT_N = (long)kB*kT*kC;
constexpr long W0_N  = (long)kB*kHID*kC;
constexpr long B0_N  = (long)kB*kHID;
constexpr long W1_N  = (long)kB*kC*kHID;
constexpr long B1_N  = (long)kB*kC;
constexpr long OFF_OUT  = 0;
constexpr long OFF_NW0  = OFF_OUT  + OUT_N;
constexpr long OFF_NB0  = OFF_NW0  + W0_N;
constexpr long OFF_NW1  = OFF_NB0  + B0_N;
constexpr long OFF_NB1  = OFF_NW1  + W1_N;
constexpr long OFF_NMW0 = OFF_NB1  + B1_N;
constexpr long OFF_NMB0 = OFF_NMW0 + W0_N;
constexpr long OFF_NMW1 = OFF_NMB0 + B0_N;
constexpr long OFF_NMB1 = OFF_NMW1 + W1_N;

// ---------------- scratch (allocation-free: __device__ globals) ----------------
__device__ float g_q     [(long)kB*kT*kC];
__device__ float g_h     [(long)kB*kT*kHID];   // fwd silu hidden; reused as z in bw
__device__ float g_hh    [(long)kB*kT*kHID];   // silu(z) in bw
__device__ float g_mem   [(long)kB*kT*kC];     // mem fwd; reused as pred/dpred
__device__ float g_pooled[(long)kB*kM*kC];
__device__ float g_retr  [(long)kB*kM*kC];
__device__ float g_xa    [(long)kB*kTA*kC];
__device__ float g_hln   [(long)kB*kTA*kC];    // ln1 out; reused as ln2 out
__device__ float g_qkv   [(long)kB*kTA*3*kC];
__device__ float g_y     [(long)kB*kTA*kC];
__device__ float g_xa2   [(long)kB*kTA*kC];    // post-attn residual; mlp adds in place
__device__ float g_hfc   [(long)kB*kTA*4*kC];
__device__ float g_keys  [(long)kB*kT*kC];
__device__ float g_vals  [(long)kB*kT*kC];
__device__ float g_dh    [(long)kB*kT*kHID];   // dh -> dz in place
__device__ float g_gw0   [(long)kB*kHID*kC];
__device__ float g_gw1   [(long)kB*kC*kHID];
__device__ float g_gb0   [(long)kB*kHID];
__device__ float g_gb1   [(long)kB*kC];

// ---------------- generic tiled SGEMM ----------------
// C[m,n] = epi( sum_k A(m,k)*B(n,k) + bias[n] ) + res[m,n]
// LNT: A[m*K+k],  B[n*K+k]   (X @ W^T — the common case)
// LNN: A[m*K+k],  B[k*N+n]   (dpred @ W)
// LTN: A[k*M+m],  B[k*N+n]   (A^T @ B — weight grads)
constexpr int GBM=128, GBN=128, GBK=16;
enum { LNT=0, LNN=1, LTN=2 };
enum { EP_NONE=0, EP_SILU=1, EP_GELU=2 };

template<int LAYOUT, int EPI>
__global__ __launch_bounds__(256, 2)
void gemm_k(const float* __restrict__ A, const float* __restrict__ B,
            const float* __restrict__ bias, const float* __restrict__ res,
            float* __restrict__ C,
            int M, int N, int K,
            long sA, long sB, long sBias, long sRes, long sC)
{
    const int bz = blockIdx.z;
    A += (long)bz * sA;  B += (long)bz * sB;  C += (long)bz * sC;

    __shared__ float As[GBK][GBM+1];
    __shared__ float Bs[GBK][GBN+1];

    const int tid = threadIdx.x;
    const int tx = tid & 15;       // 16 cols of threads
    const int ty = tid >> 4;       // 16 rows of threads
    const int rowBase = blockIdx.y * GBM;
    const int colBase = blockIdx.x * GBN;

    float acc[8][8];
#pragma unroll
    for (int i=0;i<8;i++)
#pragma unroll
        for (int j=0;j<8;j++) acc[i][j]=0.f;

    for (int k0 = 0; k0 < K; k0 += GBK) {
#pragma unroll
        for (int it = 0; it < (GBM*GBK)/256; it++) {
            int idx = tid + it*256;
            int m, k;
            if (LAYOUT == LTN) { k = idx / GBM; m = idx - k*GBM; }   // m-contig loads
            else               { m = idx / GBK; k = idx - m*GBK; }   // k-contig loads
            int gm = rowBase + m, gk = k0 + k;
            float v = 0.f;
            if (gm < M) v = (LAYOUT == LTN) ? A[(long)gk*M + gm] : A[(long)gm*K + gk];
            As[k][m] = v;
        }
#pragma unroll
        for (int it = 0; it < (GBN*GBK)/256; it++) {
            int idx = tid + it*256;
            int n, k;
            if (LAYOUT == LNT) { n = idx / GBK; k = idx - n*GBK; }
            else               { k = idx / GBN; n = idx - k*GBN; }
            int gn = colBase + n, gk = k0 + k;
            float v = 0.f;
            if (gn < N) v = (LAYOUT == LNT) ? B[(long)gn*K + gk] : B[(long)gk*N + gn];
            Bs[k][n] = v;
        }
        __syncthreads();
#pragma unroll
        for (int k=0;k<GBK;k++){
            float af[8], bf[8];
#pragma unroll
            for (int i=0;i<8;i++) af[i]=As[k][ty + i*16];
#pragma unroll
            for (int j=0;j<8;j++) bf[j]=Bs[k][tx + j*16];
#pragma unroll
            for (int i=0;i<8;i++)
#pragma unroll
                for (int j=0;j<8;j++) acc[i][j] = fmaf(af[i], bf[j], acc[i][j]);
        }
        __syncthreads();
    }

    const float* biasp = bias ? bias + (long)bz*sBias : nullptr;
    const float* resp  = res  ? res  + (long)bz*sRes  : nullptr;
#pragma unroll
    for (int i=0;i<8;i++){
        int gm = rowBase + ty + i*16;
        if (gm >= M) continue;
#pragma unroll
        for (int j=0;j<8;j++){
            int gn = colBase + tx + j*16;
            if (gn >= N) continue;
            float v = acc[i][j];
            if (biasp) v += biasp[gn];
            if (EPI == EP_SILU) v = v / (1.f + __expf(-v));
            if (EPI == EP_GELU) v = 0.5f*v*(1.f + erff(v*0.70710678118654752f));
            if (resp) v += resp[(long)gm*N + gn];
            C[(long)gm*N + gn] = v;
        }
    }
}

// ---------------- flash attention: warp per query row, 8 rows per block ----------------
__global__ __launch_bounds__(256)
void attn_k(const float* __restrict__ qkv, float* __restrict__ y)
{
    __shared__ float Ks[32][65];
    __shared__ float Vs[32][65];
    __shared__ float qs[8][64];
    __shared__ float ps[8][32];

    const int bh = blockIdx.y;              // b*H + h
    const int b = bh / kH, h = bh % kH;
    const int qi0 = blockIdx.x * 8;
    const int w = threadIdx.x >> 5, lane = threadIdx.x & 31;
    const int qi = qi0 + w;
    const bool active = qi < kTA;

    if (active) {
        long qb = (long)(b*kTA + qi)*3*kC + h*kDH;
        qs[w][lane]      = qkv[qb + lane];
        qs[w][lane + 32] = qkv[qb + lane + 32];
    }
    const int kmax = active ? ((qi < kPRE) ? (kTA-1) : qi) : -1;
    int blockKmax = (qi0 < kPRE) ? (kTA-1) : (qi0+7 < kTA ? qi0+7 : kTA-1);
    const int ntiles = blockKmax/32 + 1;

    float m = -INFINITY, l = 0.f, acc0 = 0.f, acc1 = 0.f;

    for (int t = 0; t < ntiles; t++) {
        const int kj0 = t*32;
        __syncthreads();
        for (int idx = threadIdx.x; idx < 32*64; idx += 256) {
            int r = idx >> 6, d = idx & 63;
            int kj = kj0 + r;
            float kv = 0.f, vv = 0.f;
            if (kj < kTA) {
                long base = (long)(b*kTA + kj)*3*kC + h*kDH + d;
                kv = qkv[base + kC];
                vv = qkv[base + 2*kC];
            }
            Ks[r][d] = kv;  Vs[r][d] = vv;
        }
        __syncthreads();
        if (active) {
            int kj = kj0 + lane;
            float s = -INFINITY;
            if (kj <= kmax) {
                s = 0.f;
#pragma unroll
                for (int d=0; d<64; d++) s = fmaf(qs[w][d], Ks[lane][d], s);
                s *= 0.125f;   // 1/sqrt(64)
            }
            float mt = s;
#pragma unroll
            for (int o=16;o;o>>=1) mt = fmaxf(mt, __shfl_xor_sync(0xffffffffu, mt, o));
            float mnew = fmaxf(m, mt);
            float p    = (kj <= kmax) ? __expf(s - mnew) : 0.f;
            float corr = (m == -INFINITY) ? 0.f : __expf(m - mnew);
            float psum = p;
#pragma unroll
            for (int o=16;o;o>>=1) psum += __shfl_xor_sync(0xffffffffu, psum, o);
            l = l*corr + psum;
            acc0 *= corr; acc1 *= corr;
            ps[w][lane] = p;
            __syncwarp();
#pragma unroll
            for (int j=0;j<32;j++){
                float pj = ps[w][j];
                acc0 = fmaf(pj, Vs[j][lane],      acc0);
                acc1 = fmaf(pj, Vs[j][lane + 32], acc1);
            }
            m = mnew;
        }
    }
    if (active) {
        long o = (long)(b*kTA + qi)*kC + h*kDH + lane;
        float inv = 1.f / l;
        y[o]      = acc0 * inv;
        y[o + 32] = acc1 * inv;
    }
}

// ---------------- layernorm: block per row ----------------
__global__ __launch_bounds__(256)
void ln_k(const float* __restrict__ x, const float* __restrict__ w,
          const float* __restrict__ b, float* __restrict__ o)
{
    const long row = blockIdx.x;
    const float* xr = x + row*kC;
    float s = 0.f, s2 = 0.f;
    for (int c = threadIdx.x; c < kC; c += 256) { float v = xr[c]; s += v; s2 += v*v; }
    __shared__ float sh[64];
#pragma unroll
    for (int off=16;off;off>>=1){ s += __shfl_xor_sync(0xffffffffu,s,off); s2 += __shfl_xor_sync(0xffffffffu,s2,off); }
    int wid = threadIdx.x >> 5, lane = threadIdx.x & 31;
    if (lane == 0){ sh[wid] = s; sh[32+wid] = s2; }
    __syncthreads();
    if (threadIdx.x < 32) {
        s  = (lane < 8) ? sh[lane]    : 0.f;
        s2 = (lane < 8) ? sh[32+lane] : 0.f;
#pragma unroll
        for (int off=4;off;off>>=1){ s += __shfl_xor_sync(0xffffffffu,s,off); s2 += __shfl_xor_sync(0xffffffffu,s2,off); }
        if (lane == 0){ sh[0] = s; sh[1] = s2; }
    }
    __syncthreads();
    float mean = sh[0] * (1.f/kC);
    float var  = sh[1] * (1.f/kC) - mean*mean;
    float rstd = rsqrtf(var + 1e-5f);
    for (int c = threadIdx.x; c < kC; c += 256)
        o[row*kC + c] = (xr[c]-mean)*rstd*w[c] + b[c];
}

// ---------------- small kernels ----------------
__global__ void pool_k(const float* __restrict__ mem, float* __restrict__ pooled)
{
    const int bm = blockIdx.x;                 // b*kM + m
    const int bI = bm / kM, mI = bm % kM;
    const int seg = kT / kM;                   // 64
    const float* src = mem + ((long)bI*kT + (long)mI*seg)*kC;
    for (int c = threadIdx.x; c < kC; c += blockDim.x) {
        float s = 0.f;
        for (int t = 0; t < seg; t++) s += src[(long)t*kC + c];
        pooled[(long)bm*kC + c] = s * (1.f/seg);
    }
}

__global__ void concat_k(const float* __restrict__ retr, const float* __restrict__ pm,
                         const float* __restrict__ x, float* __restrict__ xa)
{
    long i = (long)blockIdx.x*blockDim.x + threadIdx.x;
    if (i >= (long)kB*kTA*kC) return;
    int c = (int)(i % kC); long r = i / kC; int t = (int)(r % kTA); int b = (int)(r / kTA);
    float v;
    if (t < kM)        v = retr[((long)b*kM + t)*kC + c];
    else if (t < kPRE) v = pm[(long)(t-kM)*kC + c];
    else               v = x[((long)b*kT + (t-kPRE))*kC + c];
    xa[i] = v;
}

__global__ void copyout_k(const float* __restrict__ xa2, float* __restrict__ out)
{
    long i = (long)blockIdx.x*blockDim.x + threadIdx.x;
    if (i >= OUT_N) return;
    int c = (int)(i % kC); long r = i / kC; int t = (int)(r % kT); int b = (int)(r / kT);
    out[i] = xa2[((long)b*kTA + kPRE + t)*kC + c];
}

__global__ void silu_k(const float* __restrict__ z, float* __restrict__ o, long n)
{
    long i = (long)blockIdx.x*blockDim.x + threadIdx.x;
    if (i >= n) return;
    float v = z[i];
    o[i] = v / (1.f + __expf(-v));
}

__global__ void dpred_k(float* __restrict__ p, const float* __restrict__ v, long n, float scale)
{
    long i = (long)blockIdx.x*blockDim.x + threadIdx.x;
    if (i >= n) return;
    p[i] = (p[i] - v[i]) * scale;
}

__global__ void dsilu_mul_k(float* __restrict__ dh, const float* __restrict__ z, long n)
{
    long i = (long)blockIdx.x*blockDim.x + threadIdx.x;
    if (i >= n) return;
    float zz = z[i];
    float sig = 1.f / (1.f + __expf(-zz));
    dh[i] *= sig * (1.f + zz*(1.f - sig));
}

__global__ void zero_k(float* __restrict__ a, long n)
{
    long i = (long)blockIdx.x*blockDim.x + threadIdx.x;
    if (i < n) a[i] = 0.f;
}

// segmented column sum with atomics: out[j] += sum_{t in seg} in[t*cols+j]
__global__ void colsum_k(const float* __restrict__ in, float* __restrict__ out,
                         int rows, int cols, int rowsPerSeg)
{
    int z = blockIdx.z;
    in  += (long)z*rows*cols;
    out += (long)z*cols;
    int j = blockIdx.x*blockDim.x + threadIdx.x;
    if (j >= cols) return;
    int t0 = blockIdx.y * rowsPerSeg;
    int t1 = t0 + rowsPerSeg; if (t1 > rows) t1 = rows;
    float s = 0.f;
    for (int t = t0; t < t1; t++) s += in[(long)t*cols + j];
    atomicAdd(out + j, s);
}

__global__ void update_k(const float* __restrict__ w, const float* __restrict__ mom,
                         const float* __restrict__ g, float* __restrict__ outW,
                         float* __restrict__ outM, long n)
{
    long i = (long)blockIdx.x*blockDim.x + threadIdx.x;
    if (i >= n) return;
    float nm = kMU*mom[i] + g[i];
    outM[i] = nm;
    outW[i] = (1.f - kDECAY)*w[i] - kLR*nm;
}

// ---------------- host side ----------------
template<int L,int E>
static void rungemm(const float* A, const float* Bm, const float* bias, const float* res,
                    float* Cm, int M, int N, int K, int batch,
                    long sA, long sB, long sBias, long sC, long sRes = 0)
{
    dim3 grid((N+GBN-1)/GBN, (M+GBM-1)/GBM, batch);
    gemm_k<L,E><<<grid,256>>>(A,Bm,bias,res,Cm,M,N,K,sA,sB,sBias,sRes,sC);
}

static inline long cdiv(long a, long b){ return (a + b - 1)/b; }

#define GETSYM(var, symname) float* var; { void* _p = nullptr; cudaGetSymbolAddress(&_p, symname); var = (float*)_p; }

extern "C" void kernel_launch(void* const* d_in, const int* in_sizes, int n_in,
                              void* d_out, int out_size)
{
    const float* x       = (const float*)d_in[0];
    const float* persist = (const float*)d_in[1];
    const float* ln1w    = (const float*)d_in[2];
    const float* ln1b    = (const float*)d_in[3];
    const float* ln2w    = (const float*)d_in[4];
    const float* ln2b    = (const float*)d_in[5];
    const float* attnw   = (const float*)d_in[6];
    const float* attnb   = (const float*)d_in[7];
    const float* projw   = (const float*)d_in[8];
    const float* projb   = (const float*)d_in[9];
    const float* fcw     = (const float*)d_in[10];
    const float* fcb     = (const float*)d_in[11];
    const float* mlpw    = (const float*)d_in[12];
    const float* mlpb    = (const float*)d_in[13];
    const float* qw      = (const float*)d_in[14];
    const float* qb      = (const float*)d_in[15];
    const float* kw      = (const float*)d_in[16];
    const float* kb      = (const float*)d_in[17];
    const float* vw      = (const float*)d_in[18];
    const float* vb      = (const float*)d_in[19];
    const float* ow      = (const float*)d_in[20];
    const float* ob      = (const float*)d_in[21];
    const float* memw0   = (const float*)d_in[22];
    const float* memb0   = (const float*)d_in[23];
    const float* memw1   = (const float*)d_in[24];
    const float* memb1   = (const float*)d_in[25];
    const float* momw0   = (const float*)d_in[26];
    const float* momb0   = (const float*)d_in[27];
    const float* momw1   = (const float*)d_in[28];
    const float* momb1   = (const float*)d_in[29];
    float* out = (float*)d_out;

    GETSYM(q,      g_q);     GETSYM(hbuf,  g_h);     GETSYM(hh,    g_hh);
    GETSYM(memb,   g_mem);   GETSYM(pooled,g_pooled);GETSYM(retr,  g_retr);
    GETSYM(xa,     g_xa);    GETSYM(hln,   g_hln);   GETSYM(qkv,   g_qkv);
    GETSYM(y,      g_y);     GETSYM(xa2,   g_xa2);   GETSYM(hfc,   g_hfc);
    GETSYM(keys,   g_keys);  GETSYM(vals,  g_vals);  GETSYM(dh,    g_dh);
    GETSYM(gw0,    g_gw0);   GETSYM(gw1,   g_gw1);   GETSYM(gb0,   g_gb0);
    GETSYM(gb1,    g_gb1);

    const long sTC  = (long)kT*kC;
    const long sTH  = (long)kT*kHID;
    const long sW0  = (long)kHID*kC;
    const long sW1  = (long)kC*kHID;

    // --- forward memory read path ---
    // q = x @ q_w^T + q_b
    rungemm<LNT,EP_NONE>(x, qw, qb, nullptr, q, kB*kT, kC, kC, 1, 0,0,0,0);
    // h = silu(q @ w0^T + b0)  (per batch)
    rungemm<LNT,EP_SILU>(q, memw0, memb0, nullptr, hbuf, kT, kHID, kC, kB, sTC, sW0, kHID, sTH);
    // mem = h @ w1^T + b1      (per batch)
    rungemm<LNT,EP_NONE>(hbuf, memw1, memb1, nullptr, memb, kT, kC, kHID, kB, sTH, sW1, kC, sTC);
    // pooled mean over 64-token segments
    pool_k<<<kB*kM, 256>>>(memb, pooled);
    // retrieved = pooled @ o_w^T + o_b
    rungemm<LNT,EP_NONE>(pooled, ow, ob, nullptr, retr, kB*kM, kC, kC, 1, 0,0,0,0);
    // xa = concat(retrieved, persist, x)
    {
        long n = (long)kB*kTA*kC;
        concat_k<<<(unsigned)cdiv(n,256),256>>>(retr, persist, x, xa);
    }

    // --- transformer block ---
    ln_k<<<kB*kTA,256>>>(xa, ln1w, ln1b, hln);
    rungemm<LNT,EP_NONE>(hln, attnw, attnb, nullptr, qkv, kB*kTA, 3*kC, kC, 1, 0,0,0,0);
    attn_k<<<dim3((kTA+7)/8, kB*kH),256>>>(qkv, y);
    // xa2 = xa + y @ proj^T + b
    rungemm<LNT,EP_NONE>(y, projw, projb, xa, xa2, kB*kTA, kC, kC, 1, 0,0,0,0,0);
    ln_k<<<kB*kTA,256>>>(xa2, ln2w, ln2b, hln);          // hln reused as h2
    rungemm<LNT,EP_GELU>(hln, fcw, fcb, nullptr, hfc, kB*kTA, 4*kC, kC, 1, 0,0,0,0);
    // xa2 += hfc @ mlp^T + b   (in place residual)
    rungemm<LNT,EP_NONE>(hfc, mlpw, mlpb, xa2, xa2, kB*kTA, kC, 4*kC, 1, 0,0,0,0,0);
    // out = xa2[:, PRE:, :]
    copyout_k<<<(unsigned)cdiv(OUT_N,256),256>>>(xa2, out);

    // --- memory write path (one SGD-with-momentum step) ---
    rungemm<LNT,EP_NONE>(out, kw, kb, nullptr, keys, kB*kT, kC, kC, 1, 0,0,0,0);
    rungemm<LNT,EP_NONE>(out, vw, vb, nullptr, vals, kB*kT, kC, kC, 1, 0,0,0,0);
    // z = keys @ w0^T + b0  -> hbuf (reused as z)
    rungemm<LNT,EP_NONE>(keys, memw0, memb0, nullptr, hbuf, kT, kHID, kC, kB, sTC, sW0, kHID, sTH);
    {
        long n = (long)kB*kT*kHID;
        silu_k<<<(unsigned)cdiv(n,256),256>>>(hbuf, hh, n);
    }
    // pred = hh @ w1^T + b1 -> memb (reused as pred)
    rungemm<LNT,EP_NONE>(hh, memw1, memb1, nullptr, memb, kT, kC, kHID, kB, sTH, sW1, kC, sTC);
    {
        long n = (long)kB*kT*kC;
        dpred_k<<<(unsigned)cdiv(n,256),256>>>(memb, vals, n, 2.f/((float)kT*(float)kC));
    }
    // zero small grad-bias accumulators
    zero_k<<<(unsigned)cdiv(B0_N,256),256>>>(gb0, B0_N);
    zero_k<<<(unsigned)cdiv(B1_N,256),256>>>(gb1, B1_N);
    // g_b1 = colsum(dpred)
    colsum_k<<<dim3((kC+255)/256, 8, kB),256>>>(memb, gb1, kT, kC, kT/8);
    // g_w1[c,h] = sum_t dpred[t,c]*hh[t,h]   (TN)
    rungemm<LTN,EP_NONE>(memb, hh, nullptr, nullptr, gw1, kC, kHID, kT, kB, sTC, sTH, 0, sW1);
    // dh = dpred @ w1  (NN)
    rungemm<LNN,EP_NONE>(memb, memw1, nullptr, nullptr, dh, kT, kHID, kC, kB, sTC, sW1, 0, sTH);
    // dz = dh * silu'(z)
    {
        long n = (long)kB*kT*kHID;
        dsilu_mul_k<<<(unsigned)cdiv(n,256),256>>>(dh, hbuf, n);
    }
    // g_b0 = colsum(dz)
    colsum_k<<<dim3((kHID+255)/256, 8, kB),256>>>(dh, gb0, kT, kHID, kT/8);
    // g_w0[h,c] = sum_t dz[t,h]*keys[t,c]   (TN)
    rungemm<LTN,EP_NONE>(dh, keys, nullptr, nullptr, gw0, kHID, kC, kT, kB, sTH, sTC, 0, sW0);

    // --- momentum/decay updates straight into output tuple ---
    update_k<<<(unsigned)cdiv(W0_N,256),256>>>(memw0, momw0, gw0, out+OFF_NW0, out+OFF_NMW0, W0_N);
    update_k<<<(unsigned)cdiv(B0_N,256),256>>>(memb0, momb0, gb0, out+OFF_NB0, out+OFF_NMB0, B0_N);
    update_k<<<(unsigned)cdiv(W1_N,256),256>>>(memw1, momw1, gw1, out+OFF_NW1, out+OFF_NMW1, W1_N);
    update_k<<<(unsigned)cdiv(B1_N,256),256>>>(memb1, momb1, gb1, out+OFF_NB1, out+OFF_NMB1, B1_N);

    (void)in_sizes; (void)n_in; (void)out_size;
}

// round 4
// speedup vs baseline: 1.3785x; 1.3785x over previous
#include <cuda_runtime.h>
#include <math.h>
#include <stdint.h>

// ---------------- problem constants ----------------
constexpr int kB   = 8;
constexpr int kT   = 1024;
constexpr int kC   = 768;
constexpr int kH   = 12;
constexpr int kDH  = 64;
constexpr int kHID = 1536;   // 2*C
constexpr int kM   = 16;
constexpr int kP   = 4;
constexpr int kPRE = kM + kP;      // 20
constexpr int kTA  = kT + kPRE;    // 1044
constexpr float kLR = 0.01f, kMU = 0.9f, kDECAY = 0.001f;

constexpr long OUT_N = (long)kB*kT*kC;
constexpr long W0_N  = (long)kB*kHID*kC;
constexpr long B0_N  = (long)kB*kHID;
constexpr long W1_N  = (long)kB*kC*kHID;
constexpr long B1_N  = (long)kB*kC;
constexpr long OFF_OUT  = 0;
constexpr long OFF_NW0  = OFF_OUT  + OUT_N;
constexpr long OFF_NB0  = OFF_NW0  + W0_N;
constexpr long OFF_NW1  = OFF_NB0  + B0_N;
constexpr long OFF_NB1  = OFF_NW1  + W1_N;
constexpr long OFF_NMW0 = OFF_NB1  + B1_N;
constexpr long OFF_NMB0 = OFF_NMW0 + W0_N;
constexpr long OFF_NMW1 = OFF_NMB0 + B0_N;
constexpr long OFF_NMB1 = OFF_NMW1 + W1_N;

// ---------------- scratch ----------------
__device__ float g_q     [(long)kB*kT*kC];
__device__ float g_h     [(long)kB*kT*kHID];
__device__ float g_hh    [(long)kB*kT*kHID];
__device__ float g_mem   [(long)kB*kT*kC];
__device__ float g_pooled[(long)kB*kM*kC];
__device__ float g_retr  [(long)kB*kM*kC];
__device__ float g_xa    [(long)kB*kTA*kC];
__device__ float g_hln   [(long)kB*kTA*kC];
__device__ float g_qkv   [(long)kB*kTA*3*kC];
__device__ float g_y     [(long)kB*kTA*kC];
__device__ float g_xa2   [(long)kB*kTA*kC];
__device__ float g_hfc   [(long)kB*kTA*4*kC];
__device__ float g_keys  [(long)kB*kT*kC];
__device__ float g_vals  [(long)kB*kT*kC];
__device__ float g_dh    [(long)kB*kT*kHID];
__device__ float g_gw0   [(long)kB*kHID*kC];
__device__ float g_gw1   [(long)kB*kC*kHID];
__device__ float g_gb0   [(long)kB*kHID];
__device__ float g_gb1   [(long)kB*kC];
__device__ float g_w1T   [(long)kB*kHID*kC];
__device__ float g_dpT   [(long)kB*kC*kT];
__device__ float g_hhT   [(long)kB*kHID*kT];
__device__ float g_dzT   [(long)kB*kHID*kT];
__device__ float g_keysT [(long)kB*kC*kT];

// ---------------- mma.sync 3xTF32 GEMM (NT: A[M,K], B[N,K], both K-major) ----------------
constexpr int MBM = 128, MBN = 128, MBK = 16, MSTG = 3;
constexpr int STG_FLOATS = MBM*MBK + MBN*MBK;   // 4096 floats = 16KB
constexpr unsigned MSMEM = MSTG * STG_FLOATS * 4;  // 49152

enum { EP_NONE=0, EP_SILU=1, EP_GELU=2 };

__device__ __forceinline__ uint32_t smem_u32(const void* p) {
    uint32_t a;
    asm("{ .reg .u64 t; cvta.to.shared.u64 t, %1; cvt.u32.u64 %0, t; }" : "=r"(a) : "l"(p));
    return a;
}

// swizzled index within a 128x16 tile
__device__ __forceinline__ int swidx(int row, int k) {
    return row*16 + (k ^ (((row>>1)&3) << 2));
}

__device__ __forceinline__ void mma_tf32(float* d, const uint32_t* a, const uint32_t* b) {
    asm volatile(
        "mma.sync.aligned.m16n8k8.row.col.f32.tf32.tf32.f32 "
        "{%0,%1,%2,%3}, {%4,%5,%6,%7}, {%8,%9}, {%0,%1,%2,%3};"
        : "+f"(d[0]), "+f"(d[1]), "+f"(d[2]), "+f"(d[3])
        : "r"(a[0]), "r"(a[1]), "r"(a[2]), "r"(a[3]), "r"(b[0]), "r"(b[1]));
}

// split f32 -> tf32 hi + tf32 lo (3xTF32 "3M" decomposition)
__device__ __forceinline__ void tf32_split(float v, uint32_t& hi, uint32_t& lo) {
    uint32_t h;
    asm("cvt.rna.tf32.f32 %0, %1;" : "=r"(h) : "f"(v));
    float r = v - __uint_as_float(h);
    uint32_t l;
    asm("cvt.rna.tf32.f32 %0, %1;" : "=r"(l) : "f"(r));
    hi = h; lo = l;
}

template<int EPI>
__global__ __launch_bounds__(256)
void mgemm_k(const float* __restrict__ A, const float* __restrict__ B,
             const float* __restrict__ bias, const float* __restrict__ res,
             float* __restrict__ C, int M, int N, int K,
             long sA, long sB, long sBias, long sRes, long sC)
{
    extern __shared__ float smf[];
    const uint32_t smb = smem_u32(smf);

    const int tid = threadIdx.x, lane = tid & 31, wid = tid >> 5;
    const int gid = lane >> 2, tg = lane & 3;
    const int wm = wid & 3, wn = wid >> 2;
    const int bz = blockIdx.z;
    const int m0 = blockIdx.y * MBM, n0 = blockIdx.x * MBN;
    const float* Ab = A + (long)bz*sA;
    const float* Bb = B + (long)bz*sB;
    const int nk = K / MBK;

    float acc[2][8][4];
#pragma unroll
    for (int i=0;i<2;i++)
#pragma unroll
        for (int j=0;j<8;j++)
#pragma unroll
            for (int r=0;r<4;r++) acc[i][j][r] = 0.f;

    auto load_stage = [&](int stage, int kt) {
        const int sOff = stage * STG_FLOATS;
#pragma unroll
        for (int h=0; h<2; h++) {
            int c = tid + h*256;
            int row = c >> 2, kq = c & 3;
            int off = row*16 + ((kq*4) ^ (((row>>1)&3) << 2));
            {
                int gm = m0 + row;
                int ok = gm < M;
                const float* src = Ab + (long)(ok ? gm : 0)*K + kt*MBK + kq*4;
                uint32_t dst = smb + (uint32_t)(sOff + off)*4u;
                int sz = ok ? 16 : 0;
                asm volatile("cp.async.cg.shared.global [%0], [%1], 16, %2;\n"
                             :: "r"(dst), "l"(src), "r"(sz));
            }
            {
                const float* src = Bb + (long)(n0 + row)*K + kt*MBK + kq*4;
                uint32_t dst = smb + (uint32_t)(sOff + MBM*MBK + off)*4u;
                asm volatile("cp.async.cg.shared.global [%0], [%1], 16;\n"
                             :: "r"(dst), "l"(src));
            }
        }
        asm volatile("cp.async.commit_group;\n");
    };

    auto compute = [&](int stage) {
        const int sOff  = stage * STG_FLOATS;
        const int sOffB = sOff + MBM*MBK;
#pragma unroll
        for (int ks=0; ks<2; ks++) {
            const int k0 = ks*8;
            uint32_t ahi[2][4], alo[2][4], bhi[8][2], blo[8][2];
#pragma unroll
            for (int i=0;i<2;i++) {
                int r0 = wm*32 + i*16 + gid;
                float a0 = smf[sOff + swidx(r0,   k0+tg)];
                float a1 = smf[sOff + swidx(r0+8, k0+tg)];
                float a2 = smf[sOff + swidx(r0,   k0+tg+4)];
                float a3 = smf[sOff + swidx(r0+8, k0+tg+4)];
                tf32_split(a0, ahi[i][0], alo[i][0]);
                tf32_split(a1, ahi[i][1], alo[i][1]);
                tf32_split(a2, ahi[i][2], alo[i][2]);
                tf32_split(a3, ahi[i][3], alo[i][3]);
            }
#pragma unroll
            for (int j=0;j<8;j++) {
                int r = wn*64 + j*8 + gid;
                float b0 = smf[sOffB + swidx(r, k0+tg)];
                float b1 = smf[sOffB + swidx(r, k0+tg+4)];
                tf32_split(b0, bhi[j][0], blo[j][0]);
                tf32_split(b1, bhi[j][1], blo[j][1]);
            }
#pragma unroll
            for (int i=0;i<2;i++)
#pragma unroll
                for (int j=0;j<8;j++) {
                    mma_tf32(acc[i][j], alo[i], bhi[j]);
                    mma_tf32(acc[i][j], ahi[i], blo[j]);
                    mma_tf32(acc[i][j], ahi[i], bhi[j]);
                }
        }
    };

    load_stage(0, 0);
    if (nk > 1) load_stage(1, 1);
    for (int kt = 0; kt < nk; kt++) {
        if (kt + 1 < nk) asm volatile("cp.async.wait_group 1;\n");
        else             asm volatile("cp.async.wait_group 0;\n");
        __syncthreads();
        compute(kt % MSTG);
        if (kt + 2 < nk) load_stage((kt + 2) % MSTG, kt + 2);
        __syncthreads();
    }

    const float* bp   = bias ? bias + (long)bz*sBias : nullptr;
#pragma unroll
    for (int i=0;i<2;i++) {
#pragma unroll
        for (int half=0; half<2; half++) {
            int row = m0 + wm*32 + i*16 + gid + half*8;
            if (row >= M) continue;
            float* crow = C + (long)bz*sC + (long)row*N;
            const float* rrow = res ? res + (long)bz*sRes + (long)row*N : nullptr;
#pragma unroll
            for (int j=0;j<8;j++) {
                int col = n0 + wn*64 + j*8 + tg*2;
                float v0 = acc[i][j][half*2+0];
                float v1 = acc[i][j][half*2+1];
                if (bp) { v0 += bp[col]; v1 += bp[col+1]; }
                if (EPI == EP_SILU) {
                    v0 = v0 / (1.f + __expf(-v0));
                    v1 = v1 / (1.f + __expf(-v1));
                }
                if (EPI == EP_GELU) {
                    v0 = 0.5f*v0*(1.f + erff(v0*0.70710678118654752f));
                    v1 = 0.5f*v1*(1.f + erff(v1*0.70710678118654752f));
                }
                if (rrow) { v0 += rrow[col]; v1 += rrow[col+1]; }
                float2 o; o.x = v0; o.y = v1;
                *(float2*)(crow + col) = o;
            }
        }
    }
}

// ---------------- flash attention ----------------
__global__ __launch_bounds__(256)
void attn_k(const float* __restrict__ qkv, float* __restrict__ y)
{
    __shared__ float Ks[32][65];
    __shared__ float Vs[32][65];
    __shared__ float qs[8][64];
    __shared__ float ps[8][32];

    const int bh = blockIdx.y;
    const int b = bh / kH, h = bh % kH;
    const int qi0 = blockIdx.x * 8;
    const int w = threadIdx.x >> 5, lane = threadIdx.x & 31;
    const int qi = qi0 + w;
    const bool active = qi < kTA;

    if (active) {
        long qb = (long)(b*kTA + qi)*3*kC + h*kDH;
        qs[w][lane]      = qkv[qb + lane];
        qs[w][lane + 32] = qkv[qb + lane + 32];
    }
    const int kmax = active ? ((qi < kPRE) ? (kTA-1) : qi) : -1;
    int blockKmax = (qi0 < kPRE) ? (kTA-1) : (qi0+7 < kTA ? qi0+7 : kTA-1);
    const int ntiles = blockKmax/32 + 1;

    float m = -INFINITY, l = 0.f, acc0 = 0.f, acc1 = 0.f;

    for (int t = 0; t < ntiles; t++) {
        const int kj0 = t*32;
        __syncthreads();
        for (int idx = threadIdx.x; idx < 32*64; idx += 256) {
            int r = idx >> 6, d = idx & 63;
            int kj = kj0 + r;
            float kv = 0.f, vv = 0.f;
            if (kj < kTA) {
                long base = (long)(b*kTA + kj)*3*kC + h*kDH + d;
                kv = qkv[base + kC];
                vv = qkv[base + 2*kC];
            }
            Ks[r][d] = kv;  Vs[r][d] = vv;
        }
        __syncthreads();
        if (active) {
            int kj = kj0 + lane;
            float s = -INFINITY;
            if (kj <= kmax) {
                s = 0.f;
#pragma unroll
                for (int d=0; d<64; d++) s = fmaf(qs[w][d], Ks[lane][d], s);
                s *= 0.125f;
            }
            float mt = s;
#pragma unroll
            for (int o=16;o;o>>=1) mt = fmaxf(mt, __shfl_xor_sync(0xffffffffu, mt, o));
            float mnew = fmaxf(m, mt);
            float p    = (kj <= kmax) ? __expf(s - mnew) : 0.f;
            float corr = (m == -INFINITY) ? 0.f : __expf(m - mnew);
            float psum = p;
#pragma unroll
            for (int o=16;o;o>>=1) psum += __shfl_xor_sync(0xffffffffu, psum, o);
            l = l*corr + psum;
            acc0 *= corr; acc1 *= corr;
            ps[w][lane] = p;
            __syncwarp();
#pragma unroll
            for (int j=0;j<32;j++){
                float pj = ps[w][j];
                acc0 = fmaf(pj, Vs[j][lane],      acc0);
                acc1 = fmaf(pj, Vs[j][lane + 32], acc1);
            }
            m = mnew;
        }
    }
    if (active) {
        long o = (long)(b*kTA + qi)*kC + h*kDH + lane;
        float inv = 1.f / l;
        y[o]      = acc0 * inv;
        y[o + 32] = acc1 * inv;
    }
}

// ---------------- layernorm ----------------
__global__ __launch_bounds__(256)
void ln_k(const float* __restrict__ x, const float* __restrict__ w,
          const float* __restrict__ b, float* __restrict__ o)
{
    const long row = blockIdx.x;
    const float* xr = x + row*kC;
    float s = 0.f, s2 = 0.f;
    for (int c = threadIdx.x; c < kC; c += 256) { float v = xr[c]; s += v; s2 += v*v; }
    __shared__ float sh[64];
#pragma unroll
    for (int off=16;off;off>>=1){ s += __shfl_xor_sync(0xffffffffu,s,off); s2 += __shfl_xor_sync(0xffffffffu,s2,off); }
    int wid = threadIdx.x >> 5, lane = threadIdx.x & 31;
    if (lane == 0){ sh[wid] = s; sh[32+wid] = s2; }
    __syncthreads();
    if (threadIdx.x < 32) {
        s  = (lane < 8) ? sh[lane]    : 0.f;
        s2 = (lane < 8) ? sh[32+lane] : 0.f;
#pragma unroll
        for (int off=4;off;off>>=1){ s += __shfl_xor_sync(0xffffffffu,s,off); s2 += __shfl_xor_sync(0xffffffffu,s2,off); }
        if (lane == 0){ sh[0] = s; sh[1] = s2; }
    }
    __syncthreads();
    float mean = sh[0] * (1.f/kC);
    float var  = sh[1] * (1.f/kC) - mean*mean;
    float rstd = rsqrtf(var + 1e-5f);
    for (int c = threadIdx.x; c < kC; c += 256)
        o[row*kC + c] = (xr[c]-mean)*rstd*w[c] + b[c];
}

// ---------------- small kernels ----------------
__global__ void pool_k(const float* __restrict__ mem, float* __restrict__ pooled)
{
    const int bm = blockIdx.x;
    const int bI = bm / kM, mI = bm % kM;
    const int seg = kT / kM;
    const float* src = mem + ((long)bI*kT + (long)mI*seg)*kC;
    for (int c = threadIdx.x; c < kC; c += blockDim.x) {
        float s = 0.f;
        for (int t = 0; t < seg; t++) s += src[(long)t*kC + c];
        pooled[(long)bm*kC + c] = s * (1.f/seg);
    }
}

__global__ void concat_k(const float* __restrict__ retr, const float* __restrict__ pm,
                         const float* __restrict__ x, float* __restrict__ xa)
{
    long i = (long)blockIdx.x*blockDim.x + threadIdx.x;
    if (i >= (long)kB*kTA*kC) return;
    int c = (int)(i % kC); long r = i / kC; int t = (int)(r % kTA); int b = (int)(r / kTA);
    float v;
    if (t < kM)        v = retr[((long)b*kM + t)*kC + c];
    else if (t < kPRE) v = pm[(long)(t-kM)*kC + c];
    else               v = x[((long)b*kT + (t-kPRE))*kC + c];
    xa[i] = v;
}

__global__ void copyout_k(const float* __restrict__ xa2, float* __restrict__ out)
{
    long i = (long)blockIdx.x*blockDim.x + threadIdx.x;
    if (i >= OUT_N) return;
    int c = (int)(i % kC); long r = i / kC; int t = (int)(r % kT); int b = (int)(r / kT);
    out[i] = xa2[((long)b*kTA + kPRE + t)*kC + c];
}

__global__ void silu_k(const float* __restrict__ z, float* __restrict__ o, long n)
{
    long i = (long)blockIdx.x*blockDim.x + threadIdx.x;
    if (i >= n) return;
    float v = z[i];
    o[i] = v / (1.f + __expf(-v));
}

__global__ void dpred_k(float* __restrict__ p, const float* __restrict__ v, long n, float scale)
{
    long i = (long)blockIdx.x*blockDim.x + threadIdx.x;
    if (i >= n) return;
    p[i] = (p[i] - v[i]) * scale;
}

__global__ void dsilu_mul_k(float* __restrict__ dh, const float* __restrict__ z, long n)
{
    long i = (long)blockIdx.x*blockDim.x + threadIdx.x;
    if (i >= n) return;
    float zz = z[i];
    float sig = 1.f / (1.f + __expf(-zz));
    dh[i] *= sig * (1.f + zz*(1.f - sig));
}

__global__ void zero_k(float* __restrict__ a, long n)
{
    long i = (long)blockIdx.x*blockDim.x + threadIdx.x;
    if (i < n) a[i] = 0.f;
}

__global__ void colsum_k(const float* __restrict__ in, float* __restrict__ out,
                         int rows, int cols, int rowsPerSeg)
{
    int z = blockIdx.z;
    in  += (long)z*rows*cols;
    out += (long)z*cols;
    int j = blockIdx.x*blockDim.x + threadIdx.x;
    if (j >= cols) return;
    int t0 = blockIdx.y * rowsPerSeg;
    int t1 = t0 + rowsPerSeg; if (t1 > rows) t1 = rows;
    float s = 0.f;
    for (int t = t0; t < t1; t++) s += in[(long)t*cols + j];
    atomicAdd(out + j, s);
}

__global__ void update_k(const float* __restrict__ w, const float* __restrict__ mom,
                         const float* __restrict__ g, float* __restrict__ outW,
                         float* __restrict__ outM, long n)
{
    long i = (long)blockIdx.x*blockDim.x + threadIdx.x;
    if (i >= n) return;
    float nm = kMU*mom[i] + g[i];
    outM[i] = nm;
    outW[i] = (1.f - kDECAY)*w[i] - kLR*nm;
}

__global__ void transpose_k(const float* __restrict__ in, float* __restrict__ out,
                            int rows, int cols)
{
    __shared__ float tile[32][33];
    long zoff = (long)blockIdx.z * rows * cols;
    int c0 = blockIdx.x*32, r0 = blockIdx.y*32;
    int tx = threadIdx.x, ty = threadIdx.y;
#pragma unroll
    for (int i = 0; i < 32; i += 8) {
        int r = r0 + ty + i, c = c0 + tx;
        if (r < rows && c < cols) tile[ty+i][tx] = in[zoff + (long)r*cols + c];
    }
    __syncthreads();
#pragma unroll
    for (int i = 0; i < 32; i += 8) {
        int r = c0 + ty + i, c = r0 + tx;
        if (r < cols && c < rows) out[zoff + (long)r*rows + c] = tile[tx][ty+i];
    }
}

// ---------------- host side ----------------
template<int EPI>
static void mgemm(const float* A, long sA, const float* B, long sB,
                  const float* bias, long sBias, const float* res, long sRes,
                  float* C, long sC, int M, int N, int K, int batch)
{
    cudaFuncSetAttribute(mgemm_k<EPI>, cudaFuncAttributeMaxDynamicSharedMemorySize, MSMEM);
    dim3 grid(N/MBN, (M + MBM - 1)/MBM, batch);
    mgemm_k<EPI><<<grid, 256, MSMEM>>>(A, B, bias, res, C, M, N, K, sA, sB, sBias, sRes, sC);
}

static inline long cdiv(long a, long b){ return (a + b - 1)/b; }

#define GETSYM(var, symname) float* var; { void* _p = nullptr; cudaGetSymbolAddress(&_p, symname); var = (float*)_p; }

extern "C" void kernel_launch(void* const* d_in, const int* in_sizes, int n_in,
                              void* d_out, int out_size)
{
    const float* x       = (const float*)d_in[0];
    const float* persist = (const float*)d_in[1];
    const float* ln1w    = (const float*)d_in[2];
    const float* ln1b    = (const float*)d_in[3];
    const float* ln2w    = (const float*)d_in[4];
    const float* ln2b    = (const float*)d_in[5];
    const float* attnw   = (const float*)d_in[6];
    const float* attnb   = (const float*)d_in[7];
    const float* projw   = (const float*)d_in[8];
    const float* projb   = (const float*)d_in[9];
    const float* fcw     = (const float*)d_in[10];
    const float* fcb     = (const float*)d_in[11];
    const float* mlpw    = (const float*)d_in[12];
    const float* mlpb    = (const float*)d_in[13];
    const float* qw      = (const float*)d_in[14];
    const float* qb      = (const float*)d_in[15];
    const float* kw      = (const float*)d_in[16];
    const float* kb      = (const float*)d_in[17];
    const float* vw      = (const float*)d_in[18];
    const float* vb      = (const float*)d_in[19];
    const float* ow      = (const float*)d_in[20];
    const float* ob      = (const float*)d_in[21];
    const float* memw0   = (const float*)d_in[22];
    const float* memb0   = (const float*)d_in[23];
    const float* memw1   = (const float*)d_in[24];
    const float* memb1   = (const float*)d_in[25];
    const float* momw0   = (const float*)d_in[26];
    const float* momb0   = (const float*)d_in[27];
    const float* momw1   = (const float*)d_in[28];
    const float* momb1   = (const float*)d_in[29];
    float* out = (float*)d_out;

    GETSYM(q,      g_q);     GETSYM(hbuf,  g_h);     GETSYM(hh,    g_hh);
    GETSYM(memb,   g_mem);   GETSYM(pooled,g_pooled);GETSYM(retr,  g_retr);
    GETSYM(xa,     g_xa);    GETSYM(hln,   g_hln);   GETSYM(qkv,   g_qkv);
    GETSYM(y,      g_y);     GETSYM(xa2,   g_xa2);   GETSYM(hfc,   g_hfc);
    GETSYM(keys,   g_keys);  GETSYM(vals,  g_vals);  GETSYM(dh,    g_dh);
    GETSYM(gw0,    g_gw0);   GETSYM(gw1,   g_gw1);   GETSYM(gb0,   g_gb0);
    GETSYM(gb1,    g_gb1);
    GETSYM(w1T,    g_w1T);   GETSYM(dpT,   g_dpT);   GETSYM(hhT,   g_hhT);
    GETSYM(dzT,    g_dzT);   GETSYM(keysT, g_keysT);

    const long sTC  = (long)kT*kC;
    const long sTH  = (long)kT*kHID;
    const long sW0  = (long)kHID*kC;
    const long sW1  = (long)kC*kHID;

    // --- forward memory read path ---
    mgemm<EP_NONE>(x, 0, qw, 0, qb, 0, nullptr, 0, q, 0, kB*kT, kC, kC, 1);
    mgemm<EP_SILU>(q, sTC, memw0, sW0, memb0, kHID, nullptr, 0, hbuf, sTH, kT, kHID, kC, kB);
    mgemm<EP_NONE>(hbuf, sTH, memw1, sW1, memb1, kC, nullptr, 0, memb, sTC, kT, kC, kHID, kB);
    pool_k<<<kB*kM, 256>>>(memb, pooled);
    mgemm<EP_NONE>(pooled, 0, ow, 0, ob, 0, nullptr, 0, retr, 0, kB*kM, kC, kC, 1);
    {
        long n = (long)kB*kTA*kC;
        concat_k<<<(unsigned)cdiv(n,256),256>>>(retr, persist, x, xa);
    }

    // --- transformer block ---
    ln_k<<<kB*kTA,256>>>(xa, ln1w, ln1b, hln);
    mgemm<EP_NONE>(hln, 0, attnw, 0, attnb, 0, nullptr, 0, qkv, 0, kB*kTA, 3*kC, kC, 1);
    attn_k<<<dim3((kTA+7)/8, kB*kH),256>>>(qkv, y);
    mgemm<EP_NONE>(y, 0, projw, 0, projb, 0, xa, 0, xa2, 0, kB*kTA, kC, kC, 1);
    ln_k<<<kB*kTA,256>>>(xa2, ln2w, ln2b, hln);
    mgemm<EP_GELU>(hln, 0, fcw, 0, fcb, 0, nullptr, 0, hfc, 0, kB*kTA, 4*kC, kC, 1);
    mgemm<EP_NONE>(hfc, 0, mlpw, 0, mlpb, 0, xa2, 0, xa2, 0, kB*kTA, kC, 4*kC, 1);
    copyout_k<<<(unsigned)cdiv(OUT_N,256),256>>>(xa2, out);

    // --- memory write path ---
    mgemm<EP_NONE>(out, 0, kw, 0, kb, 0, nullptr, 0, keys, 0, kB*kT, kC, kC, 1);
    mgemm<EP_NONE>(out, 0, vw, 0, vb, 0, nullptr, 0, vals, 0, kB*kT, kC, kC, 1);
    mgemm<EP_NONE>(keys, sTC, memw0, sW0, memb0, kHID, nullptr, 0, hbuf, sTH, kT, kHID, kC, kB);
    {
        long n = (long)kB*kT*kHID;
        silu_k<<<(unsigned)cdiv(n,256),256>>>(hbuf, hh, n);
    }
    mgemm<EP_NONE>(hh, sTH, memw1, sW1, memb1, kC, nullptr, 0, memb, sTC, kT, kC, kHID, kB);
    {
        long n = (long)kB*kT*kC;
        dpred_k<<<(unsigned)cdiv(n,256),256>>>(memb, vals, n, 2.f/((float)kT*(float)kC));
    }
    zero_k<<<(unsigned)cdiv(B0_N,256),256>>>(gb0, B0_N);
    zero_k<<<(unsigned)cdiv(B1_N,256),256>>>(gb1, B1_N);
    colsum_k<<<dim3((kC+255)/256, 8, kB),256>>>(memb, gb1, kT, kC, kT/8);

    // transposes for grad GEMMs
    transpose_k<<<dim3(kHID/32, kC/32, kB), dim3(32,8)>>>(memw1, w1T, kC, kHID);
    transpose_k<<<dim3(kC/32,  kT/32, kB), dim3(32,8)>>>(memb, dpT, kT, kC);
    transpose_k<<<dim3(kHID/32,kT/32, kB), dim3(32,8)>>>(hh,   hhT, kT, kHID);

    // g_w1 = dpred^T @ hh
    mgemm<EP_NONE>(dpT, (long)kC*kT, hhT, (long)kHID*kT, nullptr, 0, nullptr, 0,
                   gw1, sW1, kC, kHID, kT, kB);
    // dh = dpred @ w1
    mgemm<EP_NONE>(memb, sTC, w1T, (long)kHID*kC, nullptr, 0, nullptr, 0,
                   dh, sTH, kT, kHID, kC, kB);
    {
        long n = (long)kB*kT*kHID;
        dsilu_mul_k<<<(unsigned)cdiv(n,256),256>>>(dh, hbuf, n);
    }
    colsum_k<<<dim3((kHID+255)/256, 8, kB),256>>>(dh, gb0, kT, kHID, kT/8);
    transpose_k<<<dim3(kHID/32,kT/32, kB), dim3(32,8)>>>(dh,   dzT,   kT, kHID);
    transpose_k<<<dim3(kC/32,  kT/32, kB), dim3(32,8)>>>(keys, keysT, kT, kC);
    // g_w0 = dz^T @ keys
    mgemm<EP_NONE>(dzT, (long)kHID*kT, keysT, (long)kC*kT, nullptr, 0, nullptr, 0,
                   gw0, sW0, kHID, kC, kT, kB);

    // --- updates into output tuple ---
    update_k<<<(unsigned)cdiv(W0_N,256),256>>>(memw0, momw0, gw0, out+OFF_NW0, out+OFF_NMW0, W0_N);
    update_k<<<(unsigned)cdiv(B0_N,256),256>>>(memb0, momb0, gb0, out+OFF_NB0, out+OFF_NMB0, B0_N);
    update_k<<<(unsigned)cdiv(W1_N,256),256>>>(memw1, momw1, gw1, out+OFF_NW1, out+OFF_NMW1, W1_N);
    update_k<<<(unsigned)cdiv(B1_N,256),256>>>(memb1, momb1, gb1, out+OFF_NB1, out+OFF_NMB1, B1_N);

    (void)in_sizes; (void)n_in; (void)out_size;
}

// round 6
// speedup vs baseline: 2.2965x; 1.6660x over previous
#include <cuda_runtime.h>
#include <cuda_bf16.h>
#include <math.h>
#include <stdint.h>

// ---------------- problem constants ----------------
constexpr int kB   = 8;
constexpr int kT   = 1024;
constexpr int kC   = 768;
constexpr int kH   = 12;
constexpr int kDH  = 64;
constexpr int kHID = 1536;   // 2*C
constexpr int kM   = 16;
constexpr int kP   = 4;
constexpr int kPRE = kM + kP;      // 20
constexpr int kTA  = kT + kPRE;    // 1044
constexpr float kLR = 0.01f, kMU = 0.9f, kDECAY = 0.001f;

constexpr long OUT_N = (long)kB*kT*kC;
constexpr long W0_N  = (long)kB*kHID*kC;
constexpr long B0_N  = (long)kB*kHID;
constexpr long W1_N  = (long)kB*kC*kHID;
constexpr long B1_N  = (long)kB*kC;
constexpr long OFF_NW0  = OUT_N;
constexpr long OFF_NB0  = OFF_NW0  + W0_N;
constexpr long OFF_NW1  = OFF_NB0  + B0_N;
constexpr long OFF_NB1  = OFF_NW1  + W1_N;
constexpr long OFF_NMW0 = OFF_NB1  + B1_N;
constexpr long OFF_NMB0 = OFF_NMW0 + W0_N;
constexpr long OFF_NMW1 = OFF_NMB0 + B0_N;
constexpr long OFF_NMB1 = OFF_NMW1 + W1_N;

// ---------------- f32 scratch ----------------
__device__ float g_h    [(long)kB*kT*kHID];   // z (bw)
__device__ float g_hh   [(long)kB*kT*kHID];
__device__ float g_mem  [(long)kB*kT*kC];     // mem fwd / pred / dpred
__device__ float g_retr [(long)kB*kM*kC];
__device__ float g_xa   [(long)kB*kTA*kC];
__device__ float g_qkv  [(long)kB*kTA*3*kC];
__device__ float g_xa2  [(long)kB*kTA*kC];
__device__ float g_keys [(long)kB*kT*kC];
__device__ float g_vals [(long)kB*kT*kC];
__device__ float g_dh   [(long)kB*kT*kHID];
__device__ float g_gw0  [(long)kB*kHID*kC];
__device__ float g_gw1  [(long)kB*kC*kHID];
__device__ float g_gb0  [(long)kB*kHID];
__device__ float g_gb1  [(long)kB*kC];

// ---------------- bf16 split planes (size 2*N each: [hi | lo]) ----------------
constexpr long N_X     = (long)kB*kT*kC;          // 6291456
constexpr long N_Q     = N_X;
constexpr long N_H     = (long)kB*kT*kHID;        // 12582912
constexpr long N_POOL  = (long)kB*kM*kC;          // 98304
constexpr long N_HLN   = (long)kB*kTA*kC;         // 6414336
constexpr long N_Y     = N_HLN;
constexpr long N_HFC   = (long)kB*kTA*4*kC;       // 25657344
constexpr long N_OUT   = N_X;
constexpr long N_KEYS  = N_X;
constexpr long N_HH    = N_H;
constexpr long N_DP    = N_X;
constexpr long N_DPT   = N_X;
constexpr long N_HHT   = N_H;
constexpr long N_DZT   = N_H;
constexpr long N_KEYST = N_X;
constexpr long N_W1T   = (long)kB*kHID*kC;        // 9437184
constexpr long N_SQW   = (long)kC*kC;             // 589824
constexpr long N_ATTNW = (long)3*kC*kC;
constexpr long N_FCW   = (long)4*kC*kC;
constexpr long N_MLPW  = (long)4*kC*kC;
constexpr long N_W0    = (long)kB*kHID*kC;
constexpr long N_W1    = (long)kB*kC*kHID;

__device__ __nv_bfloat16 s_x    [2*N_X];
__device__ __nv_bfloat16 s_q    [2*N_Q];
__device__ __nv_bfloat16 s_h    [2*N_H];
__device__ __nv_bfloat16 s_pool [2*N_POOL];
__device__ __nv_bfloat16 s_hln  [2*N_HLN];
__device__ __nv_bfloat16 s_y    [2*N_Y];
__device__ __nv_bfloat16 s_hfc  [2*N_HFC];
__device__ __nv_bfloat16 s_out  [2*N_OUT];
__device__ __nv_bfloat16 s_keys [2*N_KEYS];
__device__ __nv_bfloat16 s_hh   [2*N_HH];
__device__ __nv_bfloat16 s_dp   [2*N_DP];
__device__ __nv_bfloat16 s_dpT  [2*N_DPT];
__device__ __nv_bfloat16 s_hhT  [2*N_HHT];
__device__ __nv_bfloat16 s_dzT  [2*N_DZT];
__device__ __nv_bfloat16 s_keysT[2*N_KEYST];
__device__ __nv_bfloat16 s_w1T  [2*N_W1T];
__device__ __nv_bfloat16 s_qw   [2*N_SQW];
__device__ __nv_bfloat16 s_kw   [2*N_SQW];
__device__ __nv_bfloat16 s_vw   [2*N_SQW];
__device__ __nv_bfloat16 s_ow   [2*N_SQW];
__device__ __nv_bfloat16 s_projw[2*N_SQW];
__device__ __nv_bfloat16 s_attnw[2*N_ATTNW];
__device__ __nv_bfloat16 s_fcw  [2*N_FCW];
__device__ __nv_bfloat16 s_mlpw [2*N_MLPW];
__device__ __nv_bfloat16 s_w0   [2*N_W0];
__device__ __nv_bfloat16 s_w1   [2*N_W1];

// ---------------- helpers ----------------
__device__ __forceinline__ uint32_t smem_u32(const void* p) {
    uint32_t a;
    asm("{ .reg .u64 t; cvta.to.shared.u64 t, %1; cvt.u32.u64 %0, t; }" : "=r"(a) : "l"(p));
    return a;
}

__device__ __forceinline__ void bsplit(float v, __nv_bfloat16& h, __nv_bfloat16& l) {
    h = __float2bfloat16(v);
    l = __float2bfloat16(v - __bfloat162float(h));
}

__device__ __forceinline__ void mma_bf16(float* d, const uint32_t* a, const uint32_t* b) {
    asm volatile(
        "mma.sync.aligned.m16n8k16.row.col.f32.bf16.bf16.f32 "
        "{%0,%1,%2,%3}, {%4,%5,%6,%7}, {%8,%9}, {%0,%1,%2,%3};"
        : "+f"(d[0]), "+f"(d[1]), "+f"(d[2]), "+f"(d[3])
        : "r"(a[0]), "r"(a[1]), "r"(a[2]), "r"(a[3]), "r"(b[0]), "r"(b[1]));
}

// ---------------- bf16-split GEMM (NT: A[M,K], B[N,K], K-major, pre-split hi/lo) ----------------
// Block 128x128, K-slab 16, 3-stage cp.async. Stage = 4 planes (Ahi,Alo,Bhi,Blo) x 4KB = 16KB.
constexpr int MBM = 128, MBN = 128, MBK = 16, MSTG = 3;
constexpr int STG_WORDS = 4096;                 // 4 planes * 1024 words
constexpr unsigned MSMEM = MSTG * STG_WORDS * 4;  // 49152

enum { EP_NONE=0, EP_SILU=1, EP_GELU=2 };

template<int EPI, bool WF32, bool WSPLIT>
__global__ __launch_bounds__(256)
void bgemm_k(const __nv_bfloat16* __restrict__ A, const __nv_bfloat16* __restrict__ B,
             const float* __restrict__ bias, const float* __restrict__ res,
             float* __restrict__ C, __nv_bfloat16* __restrict__ Cs,
             int M, int N, int K,
             long aPlane, long bPlane, long cPlane,
             long sA, long sB, long sBias, long sRes, long sC)
{
    extern __shared__ float smf[];
    uint32_t* smu = (uint32_t*)smf;
    const uint32_t smb = smem_u32(smf);

    const int tid = threadIdx.x, lane = tid & 31, wid = tid >> 5;
    const int gid = lane >> 2, tg = lane & 3;
    const int wm = wid & 3, wn = wid >> 2;
    const int bz = blockIdx.z;
    const int m0 = blockIdx.y * MBM, n0 = blockIdx.x * MBN;
    const int nk = K / MBK;

    float acc[2][8][4];
#pragma unroll
    for (int i=0;i<2;i++)
#pragma unroll
        for (int j=0;j<8;j++)
#pragma unroll
            for (int r=0;r<4;r++) acc[i][j][r] = 0.f;

    auto load_stage = [&](int stage, int kt) {
        const int sw = stage * STG_WORDS;
#pragma unroll
        for (int it=0; it<4; it++) {
            int id = tid + it*256;
            int p = id >> 8;            // 0 Ahi, 1 Alo, 2 Bhi, 3 Blo
            int c = id & 255;
            int row = c >> 1, half = c & 1;
            const __nv_bfloat16* src;
            int sz = 16;
            if (p < 2) {
                int gm = m0 + row;
                int ok = gm < M;
                sz = ok ? 16 : 0;
                src = A + (p==1 ? aPlane : 0) + (long)bz*sA
                        + (long)(ok ? gm : 0)*K + kt*MBK + half*8;
            } else {
                src = B + (p==3 ? bPlane : 0) + (long)bz*sB
                        + (long)(n0 + row)*K + kt*MBK + half*8;
            }
            uint32_t dst = smb + (uint32_t)(sw + p*1024 + row*8
                              + ((half*4) ^ (((row>>2)&1)<<2)))*4u;
            asm volatile("cp.async.cg.shared.global [%0], [%1], 16, %2;\n"
                         :: "r"(dst), "l"(src), "r"(sz));
        }
        asm volatile("cp.async.commit_group;\n");
    };

    auto compute = [&](int stage) {
        const int sw = stage * STG_WORDS;
        uint32_t ahi[2][4], alo[2][4];
#pragma unroll
        for (int i=0;i<2;i++) {
            int r0 = wm*32 + i*16 + gid;
#pragma unroll
            for (int u=0;u<2;u++) {
                int r = r0 + u*8;
                int xr = ((r>>2)&1)<<2;
                ahi[i][u]   = smu[sw          + r*8 + (tg ^ xr)];
                ahi[i][u+2] = smu[sw          + r*8 + ((tg+4) ^ xr)];
                alo[i][u]   = smu[sw + 1024   + r*8 + (tg ^ xr)];
                alo[i][u+2] = smu[sw + 1024   + r*8 + ((tg+4) ^ xr)];
            }
        }
#pragma unroll
        for (int j=0;j<8;j++) {
            int r = wn*64 + j*8 + gid;
            int xr = ((r>>2)&1)<<2;
            uint32_t bhi[2], blo[2];
            bhi[0] = smu[sw + 2048 + r*8 + (tg ^ xr)];
            bhi[1] = smu[sw + 2048 + r*8 + ((tg+4) ^ xr)];
            blo[0] = smu[sw + 3072 + r*8 + (tg ^ xr)];
            blo[1] = smu[sw + 3072 + r*8 + ((tg+4) ^ xr)];
#pragma unroll
            for (int i=0;i<2;i++) {
                mma_bf16(acc[i][j], alo[i], bhi);
                mma_bf16(acc[i][j], ahi[i], blo);
                mma_bf16(acc[i][j], ahi[i], bhi);
            }
        }
    };

    load_stage(0, 0);
    if (nk > 1) load_stage(1, 1);
    for (int kt = 0; kt < nk; kt++) {
        if (kt + 1 < nk) asm volatile("cp.async.wait_group 1;\n");
        else             asm volatile("cp.async.wait_group 0;\n");
        __syncthreads();
        compute(kt % MSTG);
        if (kt + 2 < nk) load_stage((kt + 2) % MSTG, kt + 2);
        __syncthreads();
    }

    const float* bp = bias ? bias + (long)bz*sBias : nullptr;
#pragma unroll
    for (int i=0;i<2;i++) {
#pragma unroll
        for (int half=0; half<2; half++) {
            int row = m0 + wm*32 + i*16 + gid + half*8;
            if (row >= M) continue;
            long rbase = (long)bz*sC + (long)row*N;
#pragma unroll
            for (int j=0;j<8;j++) {
                int col = n0 + wn*64 + j*8 + tg*2;
                float v0 = acc[i][j][half*2+0];
                float v1 = acc[i][j][half*2+1];
                if (bp) { v0 += bp[col]; v1 += bp[col+1]; }
                if (EPI == EP_SILU) {
                    v0 = v0 / (1.f + __expf(-v0));
                    v1 = v1 / (1.f + __expf(-v1));
                }
                if (EPI == EP_GELU) {
                    v0 = 0.5f*v0*(1.f + erff(v0*0.70710678118654752f));
                    v1 = 0.5f*v1*(1.f + erff(v1*0.70710678118654752f));
                }
                if (res) {
                    const float* rrow = res + (long)bz*sRes + (long)row*N;
                    v0 += rrow[col]; v1 += rrow[col+1];
                }
                if (WF32) {
                    float2 o; o.x = v0; o.y = v1;
                    *(float2*)(C + rbase + col) = o;
                }
                if (WSPLIT) {
                    __nv_bfloat16 h0,l0,h1,l1;
                    bsplit(v0, h0, l0); bsplit(v1, h1, l1);
                    __nv_bfloat162 hh2; hh2.x = h0; hh2.y = h1;
                    __nv_bfloat162 ll2; ll2.x = l0; ll2.y = l1;
                    *(__nv_bfloat162*)(Cs + rbase + col) = hh2;
                    *(__nv_bfloat162*)(Cs + cPlane + rbase + col) = ll2;
                }
            }
        }
    }
}

// ---------------- flash attention (writes split y) ----------------
__global__ __launch_bounds__(256)
void attn_k(const float* __restrict__ qkv, __nv_bfloat16* __restrict__ ys, long planeN)
{
    __shared__ float Ks[32][65];
    __shared__ float Vs[32][65];
    __shared__ float qs[8][64];
    __shared__ float ps[8][32];

    const int bh = blockIdx.y;
    const int b = bh / kH, h = bh % kH;
    const int qi0 = blockIdx.x * 8;
    const int w = threadIdx.x >> 5, lane = threadIdx.x & 31;
    const int qi = qi0 + w;
    const bool active = qi < kTA;

    if (active) {
        long qb = (long)(b*kTA + qi)*3*kC + h*kDH;
        qs[w][lane]      = qkv[qb + lane];
        qs[w][lane + 32] = qkv[qb + lane + 32];
    }
    const int kmax = active ? ((qi < kPRE) ? (kTA-1) : qi) : -1;
    int blockKmax = (qi0 < kPRE) ? (kTA-1) : (qi0+7 < kTA ? qi0+7 : kTA-1);
    const int ntiles = blockKmax/32 + 1;

    float m = -INFINITY, l = 0.f, acc0 = 0.f, acc1 = 0.f;

    for (int t = 0; t < ntiles; t++) {
        const int kj0 = t*32;
        __syncthreads();
        for (int idx = threadIdx.x; idx < 32*64; idx += 256) {
            int r = idx >> 6, d = idx & 63;
            int kj = kj0 + r;
            float kv = 0.f, vv = 0.f;
            if (kj < kTA) {
                long base = (long)(b*kTA + kj)*3*kC + h*kDH + d;
                kv = qkv[base + kC];
                vv = qkv[base + 2*kC];
            }
            Ks[r][d] = kv;  Vs[r][d] = vv;
        }
        __syncthreads();
        if (active) {
            int kj = kj0 + lane;
            float s = -INFINITY;
            if (kj <= kmax) {
                s = 0.f;
#pragma unroll
                for (int d=0; d<64; d++) s = fmaf(qs[w][d], Ks[lane][d], s);
                s *= 0.125f;
            }
            float mt = s;
#pragma unroll
            for (int o=16;o;o>>=1) mt = fmaxf(mt, __shfl_xor_sync(0xffffffffu, mt, o));
            float mnew = fmaxf(m, mt);
            float p    = (kj <= kmax) ? __expf(s - mnew) : 0.f;
            float corr = (m == -INFINITY) ? 0.f : __expf(m - mnew);
            float psum = p;
#pragma unroll
            for (int o=16;o;o>>=1) psum += __shfl_xor_sync(0xffffffffu, psum, o);
            l = l*corr + psum;
            acc0 *= corr; acc1 *= corr;
            ps[w][lane] = p;
            __syncwarp();
#pragma unroll
            for (int j=0;j<32;j++){
                float pj = ps[w][j];
                acc0 = fmaf(pj, Vs[j][lane],      acc0);
                acc1 = fmaf(pj, Vs[j][lane + 32], acc1);
            }
            m = mnew;
        }
    }
    if (active) {
        long o = (long)(b*kTA + qi)*kC + h*kDH + lane;
        float inv = 1.f / l;
        float v0 = acc0 * inv, v1 = acc1 * inv;
        __nv_bfloat16 h0,l0,h1,l1;
        bsplit(v0,h0,l0); bsplit(v1,h1,l1);
        ys[o]               = h0;  ys[o + 32]           = h1;
        ys[planeN + o]      = l0;  ys[planeN + o + 32]  = l1;
    }
}

// ---------------- layernorm (writes split planes) ----------------
__global__ __launch_bounds__(256)
void ln_k(const float* __restrict__ x, const float* __restrict__ w,
          const float* __restrict__ b, __nv_bfloat16* __restrict__ o, long planeN)
{
    const long row = blockIdx.x;
    const float* xr = x + row*kC;
    float s = 0.f, s2 = 0.f;
    for (int c = threadIdx.x; c < kC; c += 256) { float v = xr[c]; s += v; s2 += v*v; }
    __shared__ float sh[64];
#pragma unroll
    for (int off=16;off;off>>=1){ s += __shfl_xor_sync(0xffffffffu,s,off); s2 += __shfl_xor_sync(0xffffffffu,s2,off); }
    int wid = threadIdx.x >> 5, lane = threadIdx.x & 31;
    if (lane == 0){ sh[wid] = s; sh[32+wid] = s2; }
    __syncthreads();
    if (threadIdx.x < 32) {
        s  = (lane < 8) ? sh[lane]    : 0.f;
        s2 = (lane < 8) ? sh[32+lane] : 0.f;
#pragma unroll
        for (int off=4;off;off>>=1){ s += __shfl_xor_sync(0xffffffffu,s,off); s2 += __shfl_xor_sync(0xffffffffu,s2,off); }
        if (lane == 0){ sh[0] = s; sh[1] = s2; }
    }
    __syncthreads();
    float mean = sh[0] * (1.f/kC);
    float var  = sh[1] * (1.f/kC) - mean*mean;
    float rstd = rsqrtf(var + 1e-5f);
    for (int c = threadIdx.x; c < kC; c += 256) {
        float v = (xr[c]-mean)*rstd*w[c] + b[c];
        __nv_bfloat16 h,lo2; bsplit(v,h,lo2);
        o[row*kC + c] = h;
        o[planeN + row*kC + c] = lo2;
    }
}

// ---------------- small kernels ----------------
__global__ void pool_k(const float* __restrict__ mem, __nv_bfloat16* __restrict__ pooled, long planeN)
{
    const int bm = blockIdx.x;
    const int bI = bm / kM, mI = bm % kM;
    const int seg = kT / kM;
    const float* src = mem + ((long)bI*kT + (long)mI*seg)*kC;
    for (int c = threadIdx.x; c < kC; c += blockDim.x) {
        float s = 0.f;
        for (int t = 0; t < seg; t++) s += src[(long)t*kC + c];
        float v = s * (1.f/seg);
        __nv_bfloat16 h,l; bsplit(v,h,l);
        pooled[(long)bm*kC + c] = h;
        pooled[planeN + (long)bm*kC + c] = l;
    }
}

__global__ void concat_k(const float* __restrict__ retr, const float* __restrict__ pm,
                         const float* __restrict__ x, float* __restrict__ xa)
{
    long i = (long)blockIdx.x*blockDim.x + threadIdx.x;
    if (i >= (long)kB*kTA*kC) return;
    int c = (int)(i % kC); long r = i / kC; int t = (int)(r % kTA); int b = (int)(r / kTA);
    float v;
    if (t < kM)        v = retr[((long)b*kM + t)*kC + c];
    else if (t < kPRE) v = pm[(long)(t-kM)*kC + c];
    else               v = x[((long)b*kT + (t-kPRE))*kC + c];
    xa[i] = v;
}

__global__ void copyout_k(const float* __restrict__ xa2, float* __restrict__ out,
                          __nv_bfloat16* __restrict__ outs, long planeN)
{
    long i = (long)blockIdx.x*blockDim.x + threadIdx.x;
    if (i >= OUT_N) return;
    int c = (int)(i % kC); long r = i / kC; int t = (int)(r % kT); int b = (int)(r / kT);
    float v = xa2[((long)b*kTA + kPRE + t)*kC + c];
    out[i] = v;
    __nv_bfloat16 h,l; bsplit(v,h,l);
    outs[i] = h; outs[planeN + i] = l;
}

__global__ void silu_k(const float* __restrict__ z, float* __restrict__ o,
                       __nv_bfloat16* __restrict__ os, long planeN, long n)
{
    long i = (long)blockIdx.x*blockDim.x + threadIdx.x;
    if (i >= n) return;
    float v = z[i];
    float r = v / (1.f + __expf(-v));
    o[i] = r;
    __nv_bfloat16 h,l; bsplit(r,h,l);
    os[i] = h; os[planeN + i] = l;
}

__global__ void dpred_k(float* __restrict__ p, const float* __restrict__ v,
                        __nv_bfloat16* __restrict__ ps, long planeN, long n, float scale)
{
    long i = (long)blockIdx.x*blockDim.x + threadIdx.x;
    if (i >= n) return;
    float r = (p[i] - v[i]) * scale;
    p[i] = r;
    __nv_bfloat16 h,l; bsplit(r,h,l);
    ps[i] = h; ps[planeN + i] = l;
}

__global__ void dsilu_mul_k(float* __restrict__ dh, const float* __restrict__ z, long n)
{
    long i = (long)blockIdx.x*blockDim.x + threadIdx.x;
    if (i >= n) return;
    float zz = z[i];
    float sig = 1.f / (1.f + __expf(-zz));
    dh[i] *= sig * (1.f + zz*(1.f - sig));
}

__global__ void zero_k(float* __restrict__ a, long n)
{
    long i = (long)blockIdx.x*blockDim.x + threadIdx.x;
    if (i < n) a[i] = 0.f;
}

__global__ void colsum_k(const float* __restrict__ in, float* __restrict__ out,
                         int rows, int cols, int rowsPerSeg)
{
    int z = blockIdx.z;
    in  += (long)z*rows*cols;
    out += (long)z*cols;
    int j = blockIdx.x*blockDim.x + threadIdx.x;
    if (j >= cols) return;
    int t0 = blockIdx.y * rowsPerSeg;
    int t1 = t0 + rowsPerSeg; if (t1 > rows) t1 = rows;
    float s = 0.f;
    for (int t = t0; t < t1; t++) s += in[(long)t*cols + j];
    atomicAdd(out + j, s);
}

__global__ void update_k(const float* __restrict__ w, const float* __restrict__ mom,
                         const float* __restrict__ g, float* __restrict__ outW,
                         float* __restrict__ outM, long n)
{
    long i = (long)blockIdx.x*blockDim.x + threadIdx.x;
    if (i >= n) return;
    float nm = kMU*mom[i] + g[i];
    outM[i] = nm;
    outW[i] = (1.f - kDECAY)*w[i] - kLR*nm;
}

// split f32 array -> bf16 hi/lo planes
__global__ void split_k(const float* __restrict__ in, __nv_bfloat16* __restrict__ out, long n)
{
    long i = (long)blockIdx.x*blockDim.x + threadIdx.x;
    if (i >= n) return;
    __nv_bfloat16 h,l; bsplit(in[i],h,l);
    out[i] = h; out[n + i] = l;
}

// transpose [rows,cols] -> [cols,rows] per batch, writing split planes
__global__ void transpose_split_k(const float* __restrict__ in, __nv_bfloat16* __restrict__ out,
                                  long planeN, int rows, int cols)
{
    __shared__ float tile[32][33];
    long zoff = (long)blockIdx.z * rows * cols;
    int c0 = blockIdx.x*32, r0 = blockIdx.y*32;
    int tx = threadIdx.x, ty = threadIdx.y;
#pragma unroll
    for (int i = 0; i < 32; i += 8) {
        int r = r0 + ty + i, c = c0 + tx;
        if (r < rows && c < cols) tile[ty+i][tx] = in[zoff + (long)r*cols + c];
    }
    __syncthreads();
#pragma unroll
    for (int i = 0; i < 32; i += 8) {
        int r = c0 + ty + i, c = r0 + tx;
        if (r < cols && c < rows) {
            __nv_bfloat16 h,l; bsplit(tile[tx][ty+i],h,l);
            out[zoff + (long)r*rows + c] = h;
            out[planeN + zoff + (long)r*rows + c] = l;
        }
    }
}

// ---------------- host side ----------------
template<int EPI, bool WF32, bool WSPLIT>
static void bgemm(const __nv_bfloat16* A, long aPlane, long sA,
                  const __nv_bfloat16* B, long bPlane, long sB,
                  const float* bias, long sBias, const float* res, long sRes,
                  float* C, __nv_bfloat16* Cs, long cPlane, long sC,
                  int M, int N, int K, int batch)
{
    cudaFuncSetAttribute(bgemm_k<EPI,WF32,WSPLIT>,
                         cudaFuncAttributeMaxDynamicSharedMemorySize, MSMEM);
    dim3 grid(N/MBN, (M + MBM - 1)/MBM, batch);
    bgemm_k<EPI,WF32,WSPLIT><<<grid, 256, MSMEM>>>(A, B, bias, res, C, Cs,
        M, N, K, aPlane, bPlane, cPlane, sA, sB, sBias, sRes, sC);
}

static inline long cdiv(long a, long b){ return (a + b - 1)/b; }

#define GETF(var, sym) float* var; { void* _p=nullptr; cudaGetSymbolAddress(&_p, sym); var=(float*)_p; }
#define GETB(var, sym) __nv_bfloat16* var; { void* _p=nullptr; cudaGetSymbolAddress(&_p, sym); var=(__nv_bfloat16*)_p; }

extern "C" void kernel_launch(void* const* d_in, const int* in_sizes, int n_in,
                              void* d_out, int out_size)
{
    const float* x       = (const float*)d_in[0];
    const float* persist = (const float*)d_in[1];
    const float* ln1w    = (const float*)d_in[2];
    const float* ln1b    = (const float*)d_in[3];
    const float* ln2w    = (const float*)d_in[4];
    const float* ln2b    = (const float*)d_in[5];
    const float* attnw   = (const float*)d_in[6];
    const float* attnb   = (const float*)d_in[7];
    const float* projw   = (const float*)d_in[8];
    const float* projb   = (const float*)d_in[9];
    const float* fcw     = (const float*)d_in[10];
    const float* fcb     = (const float*)d_in[11];
    const float* mlpw    = (const float*)d_in[12];
    const float* mlpb    = (const float*)d_in[13];
    const float* qw      = (const float*)d_in[14];
    const float* qb      = (const float*)d_in[15];
    const float* kw      = (const float*)d_in[16];
    const float* kb      = (const float*)d_in[17];
    const float* vw      = (const float*)d_in[18];
    const float* vb      = (const float*)d_in[19];
    const float* ow      = (const float*)d_in[20];
    const float* ob      = (const float*)d_in[21];
    const float* memw0   = (const float*)d_in[22];
    const float* memb0   = (const float*)d_in[23];
    const float* memw1   = (const float*)d_in[24];
    const float* memb1   = (const float*)d_in[25];
    const float* momw0   = (const float*)d_in[26];
    const float* momb0   = (const float*)d_in[27];
    const float* momw1   = (const float*)d_in[28];
    const float* momb1   = (const float*)d_in[29];
    float* out = (float*)d_out;

    GETF(zbuf, g_h);    GETF(hh, g_hh);    GETF(memb, g_mem);  GETF(retr, g_retr);
    GETF(xa, g_xa);     GETF(qkv, g_qkv);  GETF(xa2, g_xa2);   GETF(keys, g_keys);
    GETF(vals, g_vals); GETF(dh, g_dh);    GETF(gw0, g_gw0);   GETF(gw1, g_gw1);
    GETF(gb0, g_gb0);   GETF(gb1, g_gb1);

    GETB(px,    s_x);     GETB(pq,    s_q);     GETB(ph,    s_h);     GETB(ppool, s_pool);
    GETB(phln,  s_hln);   GETB(py,    s_y);     GETB(phfc,  s_hfc);   GETB(pout,  s_out);
    GETB(pkeys, s_keys);  GETB(phh,   s_hh);    GETB(pdp,   s_dp);    GETB(pdpT,  s_dpT);
    GETB(phhT,  s_hhT);   GETB(pdzT,  s_dzT);   GETB(pkeysT,s_keysT); GETB(pw1T,  s_w1T);
    GETB(pqw,   s_qw);    GETB(pkw,   s_kw);    GETB(pvw,   s_vw);    GETB(pow_,  s_ow);
    GETB(pprojw,s_projw); GETB(pattnw,s_attnw); GETB(pfcw,  s_fcw);   GETB(pmlpw, s_mlpw);
    GETB(pw0,   s_w0);    GETB(pw1,   s_w1);

    const long sTC = (long)kT*kC, sTH = (long)kT*kHID;
    const long sW0 = (long)kHID*kC, sW1 = (long)kC*kHID;

    // --- split fixed inputs ---
    auto split = [&](const float* in, __nv_bfloat16* outp, long n){
        split_k<<<(unsigned)cdiv(n,256),256>>>(in, outp, n);
    };
    split(x, px, N_X);
    split(qw, pqw, N_SQW);   split(kw, pkw, N_SQW);   split(vw, pvw, N_SQW);
    split(ow, pow_, N_SQW);  split(projw, pprojw, N_SQW);
    split(attnw, pattnw, N_ATTNW);
    split(fcw, pfcw, N_FCW); split(mlpw, pmlpw, N_MLPW);
    split(memw0, pw0, N_W0); split(memw1, pw1, N_W1);
    // w1T split (for dh GEMM B): transpose [C,HID] -> [HID,C]
    transpose_split_k<<<dim3(kHID/32, kC/32, kB), dim3(32,8)>>>(memw1, pw1T, N_W1T, kC, kHID);

    // --- forward memory read path ---
    bgemm<EP_NONE,false,true>(px,N_X,0, pqw,N_SQW,0, qb,0, nullptr,0,
                              nullptr, pq,N_Q, 0, kB*kT, kC, kC, 1);
    bgemm<EP_SILU,false,true>(pq,N_Q,sTC, pw0,N_W0,sW0, memb0,kHID, nullptr,0,
                              nullptr, ph,N_H, sTH, kT, kHID, kC, kB);
    bgemm<EP_NONE,true,false>(ph,N_H,sTH, pw1,N_W1,sW1, memb1,kC, nullptr,0,
                              memb, nullptr,0, sTC, kT, kC, kHID, kB);
    pool_k<<<kB*kM, 256>>>(memb, ppool, N_POOL);
    bgemm<EP_NONE,true,false>(ppool,N_POOL,0, pow_,N_SQW,0, ob,0, nullptr,0,
                              retr, nullptr,0, 0, kB*kM, kC, kC, 1);
    {
        long n = (long)kB*kTA*kC;
        concat_k<<<(unsigned)cdiv(n,256),256>>>(retr, persist, x, xa);
    }

    // --- transformer block ---
    ln_k<<<kB*kTA,256>>>(xa, ln1w, ln1b, phln, N_HLN);
    bgemm<EP_NONE,true,false>(phln,N_HLN,0, pattnw,N_ATTNW,0, attnb,0, nullptr,0,
                              qkv, nullptr,0, 0, kB*kTA, 3*kC, kC, 1);
    attn_k<<<dim3((kTA+7)/8, kB*kH),256>>>(qkv, py, N_Y);
    bgemm<EP_NONE,true,false>(py,N_Y,0, pprojw,N_SQW,0, projb,0, xa,0,
                              xa2, nullptr,0, 0, kB*kTA, kC, kC, 1);
    ln_k<<<kB*kTA,256>>>(xa2, ln2w, ln2b, phln, N_HLN);
    bgemm<EP_GELU,false,true>(phln,N_HLN,0, pfcw,N_FCW,0, fcb,0, nullptr,0,
                              nullptr, phfc,N_HFC, 0, kB*kTA, 4*kC, kC, 1);
    bgemm<EP_NONE,true,false>(phfc,N_HFC,0, pmlpw,N_MLPW,0, mlpb,0, xa2,0,
                              xa2, nullptr,0, 0, kB*kTA, kC, 4*kC, 1);
    copyout_k<<<(unsigned)cdiv(OUT_N,256),256>>>(xa2, out, pout, N_OUT);

    // --- memory write path ---
    bgemm<EP_NONE,true,true>(pout,N_OUT,0, pkw,N_SQW,0, kb,0, nullptr,0,
                             keys, pkeys,N_KEYS, 0, kB*kT, kC, kC, 1);
    bgemm<EP_NONE,true,false>(pout,N_OUT,0, pvw,N_SQW,0, vb,0, nullptr,0,
                              vals, nullptr,0, 0, kB*kT, kC, kC, 1);
    bgemm<EP_NONE,true,false>(pkeys,N_KEYS,sTC, pw0,N_W0,sW0, memb0,kHID, nullptr,0,
                              zbuf, nullptr,0, sTH, kT, kHID, kC, kB);
    {
        long n = (long)kB*kT*kHID;
        silu_k<<<(unsigned)cdiv(n,256),256>>>(zbuf, hh, phh, N_HH, n);
    }
    bgemm<EP_NONE,true,false>(phh,N_HH,sTH, pw1,N_W1,sW1, memb1,kC, nullptr,0,
                              memb, nullptr,0, sTC, kT, kC, kHID, kB);
    {
        long n = (long)kB*kT*kC;
        dpred_k<<<(unsigned)cdiv(n,256),256>>>(memb, vals, pdp, N_DP, n, 2.f/((float)kT*(float)kC));
    }
    zero_k<<<(unsigned)cdiv(B0_N,256),256>>>(gb0, B0_N);
    zero_k<<<(unsigned)cdiv(B1_N,256),256>>>(gb1, B1_N);
    colsum_k<<<dim3((kC+255)/256, 8, kB),256>>>(memb, gb1, kT, kC, kT/8);

    transpose_split_k<<<dim3(kC/32,  kT/32, kB), dim3(32,8)>>>(memb, pdpT, N_DPT, kT, kC);
    transpose_split_k<<<dim3(kHID/32,kT/32, kB), dim3(32,8)>>>(hh,   phhT, N_HHT, kT, kHID);

    // g_w1 = dpred^T @ hh   (A=[C,T], B=[HID,T])
    bgemm<EP_NONE,true,false>(pdpT,N_DPT,sTC, phhT,N_HHT,sTH, nullptr,0, nullptr,0,
                              gw1, nullptr,0, sW1, kC, kHID, kT, kB);
    // dh = dpred @ w1       (A=[T,C], B=w1T [HID,C])
    bgemm<EP_NONE,true,false>(pdp,N_DP,sTC, pw1T,N_W1T,sW0, nullptr,0, nullptr,0,
                              dh, nullptr,0, sTH, kT, kHID, kC, kB);
    {
        long n = (long)kB*kT*kHID;
        dsilu_mul_k<<<(unsigned)cdiv(n,256),256>>>(dh, zbuf, n);
    }
    colsum_k<<<dim3((kHID+255)/256, 8, kB),256>>>(dh, gb0, kT, kHID, kT/8);
    transpose_split_k<<<dim3(kHID/32,kT/32, kB), dim3(32,8)>>>(dh,   pdzT,  N_DZT,  kT, kHID);
    transpose_split_k<<<dim3(kC/32,  kT/32, kB), dim3(32,8)>>>(keys, pkeysT,N_KEYST,kT, kC);
    // g_w0 = dz^T @ keys    (A=[HID,T], B=[C,T])
    bgemm<EP_NONE,true,false>(pdzT,N_DZT,sTH, pkeysT,N_KEYST,sTC, nullptr,0, nullptr,0,
                              gw0, nullptr,0, sW0, kHID, kC, kT, kB);

    // --- updates into output tuple ---
    update_k<<<(unsigned)cdiv(W0_N,256),256>>>(memw0, momw0, gw0, out+OFF_NW0, out+OFF_NMW0, W0_N);
    update_k<<<(unsigned)cdiv(B0_N,256),256>>>(memb0, momb0, gb0, out+OFF_NB0, out+OFF_NMB0, B0_N);
    update_k<<<(unsigned)cdiv(W1_N,256),256>>>(memw1, momw1, gw1, out+OFF_NW1, out+OFF_NMW1, W1_N);
    update_k<<<(unsigned)cdiv(B1_N,256),256>>>(memb1, momb1, gb1, out+OFF_NB1, out+OFF_NMB1, B1_N);

    (void)in_sizes; (void)n_in; (void)out_size;
}

// round 7
// speedup vs baseline: 3.0399x; 1.3237x over previous
#include <cuda_runtime.h>
#include <cuda_bf16.h>
#include <math.h>
#include <stdint.h>

// ---------------- problem constants ----------------
constexpr int kB   = 8;
constexpr int kT   = 1024;
constexpr int kC   = 768;
constexpr int kH   = 12;
constexpr int kDH  = 64;
constexpr int kHID = 1536;   // 2*C
constexpr int kM   = 16;
constexpr int kP   = 4;
constexpr int kPRE = kM + kP;      // 20
constexpr int kTA  = kT + kPRE;    // 1044
constexpr float kLR = 0.01f, kMU = 0.9f, kDECAY = 0.001f;

constexpr long OUT_N = (long)kB*kT*kC;
constexpr long W0_N  = (long)kB*kHID*kC;
constexpr long B0_N  = (long)kB*kHID;
constexpr long W1_N  = (long)kB*kC*kHID;
constexpr long B1_N  = (long)kB*kC;
constexpr long OFF_NW0  = OUT_N;
constexpr long OFF_NB0  = OFF_NW0  + W0_N;
constexpr long OFF_NW1  = OFF_NB0  + B0_N;
constexpr long OFF_NB1  = OFF_NW1  + W1_N;
constexpr long OFF_NMW0 = OFF_NB1  + B1_N;
constexpr long OFF_NMB0 = OFF_NMW0 + W0_N;
constexpr long OFF_NMW1 = OFF_NMB0 + B0_N;
constexpr long OFF_NMB1 = OFF_NMW1 + W1_N;

// ---------------- f32 scratch ----------------
__device__ float g_h    [(long)kB*kT*kHID];   // z (bw)
__device__ float g_hh   [(long)kB*kT*kHID];
__device__ float g_mem  [(long)kB*kT*kC];     // mem fwd / pred / dpred
__device__ float g_retr [(long)kB*kM*kC];
__device__ float g_xa   [(long)kB*kTA*kC];
__device__ float g_qkv  [(long)kB*kTA*3*kC];
__device__ float g_xa2  [(long)kB*kTA*kC];
__device__ float g_keys [(long)kB*kT*kC];
__device__ float g_vals [(long)kB*kT*kC];
__device__ float g_dh   [(long)kB*kT*kHID];
__device__ float g_gw0  [(long)kB*kHID*kC];
__device__ float g_gw1  [(long)kB*kC*kHID];
__device__ float g_gb0  [(long)kB*kHID];
__device__ float g_gb1  [(long)kB*kC];

// ---------------- bf16 split planes (size 2*N each: [hi | lo]) ----------------
constexpr long N_X     = (long)kB*kT*kC;
constexpr long N_Q     = N_X;
constexpr long N_H     = (long)kB*kT*kHID;
constexpr long N_POOL  = (long)kB*kM*kC;
constexpr long N_HLN   = (long)kB*kTA*kC;
constexpr long N_Y     = N_HLN;
constexpr long N_HFC   = (long)kB*kTA*4*kC;
constexpr long N_OUT   = N_X;
constexpr long N_KEYS  = N_X;
constexpr long N_HH    = N_H;
constexpr long N_DP    = N_X;
constexpr long N_DPT   = N_X;
constexpr long N_HHT   = N_H;
constexpr long N_DZT   = N_H;
constexpr long N_KEYST = N_X;
constexpr long N_W1T   = (long)kB*kHID*kC;
constexpr long N_SQW   = (long)kC*kC;
constexpr long N_ATTNW = (long)3*kC*kC;
constexpr long N_FCW   = (long)4*kC*kC;
constexpr long N_MLPW  = (long)4*kC*kC;
constexpr long N_W0    = (long)kB*kHID*kC;
constexpr long N_W1    = (long)kB*kC*kHID;

__device__ __nv_bfloat16 s_x    [2*N_X];
__device__ __nv_bfloat16 s_q    [2*N_Q];
__device__ __nv_bfloat16 s_h    [2*N_H];
__device__ __nv_bfloat16 s_pool [2*N_POOL];
__device__ __nv_bfloat16 s_hln  [2*N_HLN];
__device__ __nv_bfloat16 s_y    [2*N_Y];
__device__ __nv_bfloat16 s_hfc  [2*N_HFC];
__device__ __nv_bfloat16 s_out  [2*N_OUT];
__device__ __nv_bfloat16 s_keys [2*N_KEYS];
__device__ __nv_bfloat16 s_hh   [2*N_HH];
__device__ __nv_bfloat16 s_dp   [2*N_DP];
__device__ __nv_bfloat16 s_dpT  [2*N_DPT];
__device__ __nv_bfloat16 s_hhT  [2*N_HHT];
__device__ __nv_bfloat16 s_dzT  [2*N_DZT];
__device__ __nv_bfloat16 s_keysT[2*N_KEYST];
__device__ __nv_bfloat16 s_w1T  [2*N_W1T];
__device__ __nv_bfloat16 s_qw   [2*N_SQW];
__device__ __nv_bfloat16 s_kw   [2*N_SQW];
__device__ __nv_bfloat16 s_vw   [2*N_SQW];
__device__ __nv_bfloat16 s_ow   [2*N_SQW];
__device__ __nv_bfloat16 s_projw[2*N_SQW];
__device__ __nv_bfloat16 s_attnw[2*N_ATTNW];
__device__ __nv_bfloat16 s_fcw  [2*N_FCW];
__device__ __nv_bfloat16 s_mlpw [2*N_MLPW];
__device__ __nv_bfloat16 s_w0   [2*N_W0];
__device__ __nv_bfloat16 s_w1   [2*N_W1];

// ---------------- helpers ----------------
__device__ __forceinline__ uint32_t smem_u32(const void* p) {
    uint32_t a;
    asm("{ .reg .u64 t; cvta.to.shared.u64 t, %1; cvt.u32.u64 %0, t; }" : "=r"(a) : "l"(p));
    return a;
}

__device__ __forceinline__ void bsplit(float v, __nv_bfloat16& h, __nv_bfloat16& l) {
    h = __float2bfloat16(v);
    l = __float2bfloat16(v - __bfloat162float(h));
}

__device__ __forceinline__ uint32_t packb(__nv_bfloat16 a, __nv_bfloat16 b) {
    __nv_bfloat162 t; t.x = a; t.y = b;
    return *(uint32_t*)&t;
}

__device__ __forceinline__ void mma_bf16(float* d, const uint32_t* a, const uint32_t* b) {
    asm volatile(
        "mma.sync.aligned.m16n8k16.row.col.f32.bf16.bf16.f32 "
        "{%0,%1,%2,%3}, {%4,%5,%6,%7}, {%8,%9}, {%0,%1,%2,%3};"
        : "+f"(d[0]), "+f"(d[1]), "+f"(d[2]), "+f"(d[3])
        : "r"(a[0]), "r"(a[1]), "r"(a[2]), "r"(a[3]), "r"(b[0]), "r"(b[1]));
}

// ---------------- bf16-split GEMM (NT, unchanged from R5) ----------------
constexpr int MBM = 128, MBN = 128, MBK = 16, MSTG = 3;
constexpr int STG_WORDS = 4096;
constexpr unsigned MSMEM = MSTG * STG_WORDS * 4;

enum { EP_NONE=0, EP_SILU=1, EP_GELU=2 };

template<int EPI, bool WF32, bool WSPLIT>
__global__ __launch_bounds__(256)
void bgemm_k(const __nv_bfloat16* __restrict__ A, const __nv_bfloat16* __restrict__ B,
             const float* __restrict__ bias, const float* __restrict__ res,
             float* __restrict__ C, __nv_bfloat16* __restrict__ Cs,
             int M, int N, int K,
             long aPlane, long bPlane, long cPlane,
             long sA, long sB, long sBias, long sRes, long sC)
{
    extern __shared__ float smf[];
    uint32_t* smu = (uint32_t*)smf;
    const uint32_t smb = smem_u32(smf);

    const int tid = threadIdx.x, lane = tid & 31, wid = tid >> 5;
    const int gid = lane >> 2, tg = lane & 3;
    const int wm = wid & 3, wn = wid >> 2;
    const int bz = blockIdx.z;
    const int m0 = blockIdx.y * MBM, n0 = blockIdx.x * MBN;
    const int nk = K / MBK;

    float acc[2][8][4];
#pragma unroll
    for (int i=0;i<2;i++)
#pragma unroll
        for (int j=0;j<8;j++)
#pragma unroll
            for (int r=0;r<4;r++) acc[i][j][r] = 0.f;

    auto load_stage = [&](int stage, int kt) {
        const int sw = stage * STG_WORDS;
#pragma unroll
        for (int it=0; it<4; it++) {
            int id = tid + it*256;
            int p = id >> 8;
            int c = id & 255;
            int row = c >> 1, half = c & 1;
            const __nv_bfloat16* src;
            int sz = 16;
            if (p < 2) {
                int gm = m0 + row;
                int ok = gm < M;
                sz = ok ? 16 : 0;
                src = A + (p==1 ? aPlane : 0) + (long)bz*sA
                        + (long)(ok ? gm : 0)*K + kt*MBK + half*8;
            } else {
                src = B + (p==3 ? bPlane : 0) + (long)bz*sB
                        + (long)(n0 + row)*K + kt*MBK + half*8;
            }
            uint32_t dst = smb + (uint32_t)(sw + p*1024 + row*8
                              + ((half*4) ^ (((row>>2)&1)<<2)))*4u;
            asm volatile("cp.async.cg.shared.global [%0], [%1], 16, %2;\n"
                         :: "r"(dst), "l"(src), "r"(sz));
        }
        asm volatile("cp.async.commit_group;\n");
    };

    auto compute = [&](int stage) {
        const int sw = stage * STG_WORDS;
        uint32_t ahi[2][4], alo[2][4];
#pragma unroll
        for (int i=0;i<2;i++) {
            int r0 = wm*32 + i*16 + gid;
#pragma unroll
            for (int u=0;u<2;u++) {
                int r = r0 + u*8;
                int xr = ((r>>2)&1)<<2;
                ahi[i][u]   = smu[sw          + r*8 + (tg ^ xr)];
                ahi[i][u+2] = smu[sw          + r*8 + ((tg+4) ^ xr)];
                alo[i][u]   = smu[sw + 1024   + r*8 + (tg ^ xr)];
                alo[i][u+2] = smu[sw + 1024   + r*8 + ((tg+4) ^ xr)];
            }
        }
#pragma unroll
        for (int j=0;j<8;j++) {
            int r = wn*64 + j*8 + gid;
            int xr = ((r>>2)&1)<<2;
            uint32_t bhi[2], blo[2];
            bhi[0] = smu[sw + 2048 + r*8 + (tg ^ xr)];
            bhi[1] = smu[sw + 2048 + r*8 + ((tg+4) ^ xr)];
            blo[0] = smu[sw + 3072 + r*8 + (tg ^ xr)];
            blo[1] = smu[sw + 3072 + r*8 + ((tg+4) ^ xr)];
#pragma unroll
            for (int i=0;i<2;i++) {
                mma_bf16(acc[i][j], alo[i], bhi);
                mma_bf16(acc[i][j], ahi[i], blo);
                mma_bf16(acc[i][j], ahi[i], bhi);
            }
        }
    };

    load_stage(0, 0);
    if (nk > 1) load_stage(1, 1);
    for (int kt = 0; kt < nk; kt++) {
        if (kt + 1 < nk) asm volatile("cp.async.wait_group 1;\n");
        else             asm volatile("cp.async.wait_group 0;\n");
        __syncthreads();
        compute(kt % MSTG);
        if (kt + 2 < nk) load_stage((kt + 2) % MSTG, kt + 2);
        __syncthreads();
    }

    const float* bp = bias ? bias + (long)bz*sBias : nullptr;
#pragma unroll
    for (int i=0;i<2;i++) {
#pragma unroll
        for (int half=0; half<2; half++) {
            int row = m0 + wm*32 + i*16 + gid + half*8;
            if (row >= M) continue;
            long rbase = (long)bz*sC + (long)row*N;
#pragma unroll
            for (int j=0;j<8;j++) {
                int col = n0 + wn*64 + j*8 + tg*2;
                float v0 = acc[i][j][half*2+0];
                float v1 = acc[i][j][half*2+1];
                if (bp) { v0 += bp[col]; v1 += bp[col+1]; }
                if (EPI == EP_SILU) {
                    v0 = v0 / (1.f + __expf(-v0));
                    v1 = v1 / (1.f + __expf(-v1));
                }
                if (EPI == EP_GELU) {
                    v0 = 0.5f*v0*(1.f + erff(v0*0.70710678118654752f));
                    v1 = 0.5f*v1*(1.f + erff(v1*0.70710678118654752f));
                }
                if (res) {
                    const float* rrow = res + (long)bz*sRes + (long)row*N;
                    v0 += rrow[col]; v1 += rrow[col+1];
                }
                if (WF32) {
                    float2 o; o.x = v0; o.y = v1;
                    *(float2*)(C + rbase + col) = o;
                }
                if (WSPLIT) {
                    __nv_bfloat16 h0,l0,h1,l1;
                    bsplit(v0, h0, l0); bsplit(v1, h1, l1);
                    *(__nv_bfloat162*)(Cs + rbase + col) = __nv_bfloat162{h0,h1};
                    *(__nv_bfloat162*)(Cs + cPlane + rbase + col) = __nv_bfloat162{l0,l1};
                }
            }
        }
    }
}

// ---------------- mma flash attention ----------------
// Block: 128 threads (4 warps), 64 queries of one (b,h). Key tiles of 32.
// Q/K stored [row][d] bf16 hi/lo, row stride 72 bf16 (36 words).
// V stored transposed [d][key], row stride 40 bf16 (20 words).
__global__ __launch_bounds__(128)
void attn_mma_k(const float* __restrict__ qkv, __nv_bfloat16* __restrict__ ys, long planeN)
{
    __shared__ __nv_bfloat16 Qh[64*72], Ql[64*72];
    __shared__ __nv_bfloat16 Kh[32*72], Kl[32*72];
    __shared__ __nv_bfloat16 Vh[64*40], Vl[64*40];

    const int bh = blockIdx.y;
    const int bb = bh / kH, hh = bh % kH;
    const int q0 = blockIdx.x * 64;
    const int tid = threadIdx.x, lane = tid & 31, wq = tid >> 5;
    const int gid = lane >> 2, tg = lane & 3;

    const uint32_t* Qwh = (const uint32_t*)Qh;
    const uint32_t* Qwl = (const uint32_t*)Ql;
    const uint32_t* Kwh = (const uint32_t*)Kh;
    const uint32_t* Kwl = (const uint32_t*)Kl;
    const uint32_t* Vwh = (const uint32_t*)Vh;
    const uint32_t* Vwl = (const uint32_t*)Vl;

    // ---- load Q tile (64x64) ----
#pragma unroll
    for (int it = 0; it < 8; it++) {
        int idx = tid + it*128;          // 1024 float4 slots
        int row = idx >> 4;
        int dq  = (idx & 15) * 4;
        int qg  = q0 + row;
        float4 v = make_float4(0.f,0.f,0.f,0.f);
        if (qg < kTA)
            v = *(const float4*)&qkv[((long)(bb*kTA + qg))*3*kC + hh*kDH + dq];
        __nv_bfloat16 a0,b0,a1,b1,a2,b2,a3,b3;
        bsplit(v.x,a0,b0); bsplit(v.y,a1,b1); bsplit(v.z,a2,b2); bsplit(v.w,a3,b3);
        *(__nv_bfloat162*)&Qh[row*72 + dq]     = __nv_bfloat162{a0,a1};
        *(__nv_bfloat162*)&Qh[row*72 + dq + 2] = __nv_bfloat162{a2,a3};
        *(__nv_bfloat162*)&Ql[row*72 + dq]     = __nv_bfloat162{b0,b1};
        *(__nv_bfloat162*)&Ql[row*72 + dq + 2] = __nv_bfloat162{b2,b3};
    }
    __syncthreads();

    // ---- load Q fragments into registers ----
    uint32_t qh[4][4], ql[4][4];
    {
        int r0 = wq*16 + gid;
#pragma unroll
        for (int c = 0; c < 4; c++) {
            qh[c][0] = Qwh[ r0    *36 + 8*c + tg];
            qh[c][1] = Qwh[(r0+8) *36 + 8*c + tg];
            qh[c][2] = Qwh[ r0    *36 + 8*c + tg + 4];
            qh[c][3] = Qwh[(r0+8) *36 + 8*c + tg + 4];
            ql[c][0] = Qwl[ r0    *36 + 8*c + tg];
            ql[c][1] = Qwl[(r0+8) *36 + 8*c + tg];
            ql[c][2] = Qwl[ r0    *36 + 8*c + tg + 4];
            ql[c][3] = Qwl[(r0+8) *36 + 8*c + tg + 4];
        }
    }

    float yacc[8][4];
#pragma unroll
    for (int f=0; f<8; f++)
#pragma unroll
        for (int e=0; e<4; e++) yacc[f][e] = 0.f;
    float mrow0 = -INFINITY, mrow1 = -INFINITY, lrow0 = 0.f, lrow1 = 0.f;

    const int qrow0 = q0 + wq*16 + gid;
    const int qrow1 = qrow0 + 8;

    int ntiles = (q0 == 0) ? (kTA + 31)/32 : (q0/32 + 2);
    if (ntiles > (kTA + 31)/32) ntiles = (kTA + 31)/32;

    for (int kt = 0; kt < ntiles; kt++) {
        __syncthreads();
        // ---- load K tile [32 x 64] and V tile (transposed) ----
#pragma unroll
        for (int it = 0; it < 4; it++) {
            int idx = tid + it*128;      // 512 float4 slots
            int row = idx >> 4;
            int dq  = (idx & 15) * 4;
            int kg  = kt*32 + row;
            long base = ((long)(bb*kTA + (kg < kTA ? kg : 0)))*3*kC + hh*kDH + dq;
            float4 kv = make_float4(0.f,0.f,0.f,0.f), vv = make_float4(0.f,0.f,0.f,0.f);
            if (kg < kTA) {
                kv = *(const float4*)&qkv[base + kC];
                vv = *(const float4*)&qkv[base + 2*kC];
            }
            __nv_bfloat16 a0,b0,a1,b1,a2,b2,a3,b3;
            bsplit(kv.x,a0,b0); bsplit(kv.y,a1,b1); bsplit(kv.z,a2,b2); bsplit(kv.w,a3,b3);
            *(__nv_bfloat162*)&Kh[row*72 + dq]     = __nv_bfloat162{a0,a1};
            *(__nv_bfloat162*)&Kh[row*72 + dq + 2] = __nv_bfloat162{a2,a3};
            *(__nv_bfloat162*)&Kl[row*72 + dq]     = __nv_bfloat162{b0,b1};
            *(__nv_bfloat162*)&Kl[row*72 + dq + 2] = __nv_bfloat162{b2,b3};
            // V transposed
            float vs[4] = {vv.x, vv.y, vv.z, vv.w};
#pragma unroll
            for (int u = 0; u < 4; u++) {
                __nv_bfloat16 vh2, vl2; bsplit(vs[u], vh2, vl2);
                Vh[(dq+u)*40 + row] = vh2;
                Vl[(dq+u)*40 + row] = vl2;
            }
        }
        __syncthreads();

        // ---- S = Q K^T (3-product split) ----
        float sfr[4][4];
#pragma unroll
        for (int j=0;j<4;j++)
#pragma unroll
            for (int e=0;e<4;e++) sfr[j][e] = 0.f;
#pragma unroll
        for (int j = 0; j < 4; j++) {
            int kr = 8*j + gid;
#pragma unroll
            for (int c = 0; c < 4; c++) {
                uint32_t kbh[2], kbl[2];
                kbh[0] = Kwh[kr*36 + 8*c + tg];
                kbh[1] = Kwh[kr*36 + 8*c + tg + 4];
                kbl[0] = Kwl[kr*36 + 8*c + tg];
                kbl[1] = Kwl[kr*36 + 8*c + tg + 4];
                mma_bf16(sfr[j], ql[c], kbh);
                mma_bf16(sfr[j], qh[c], kbl);
                mma_bf16(sfr[j], qh[c], kbh);
            }
        }

        // ---- scale + mask ----
#pragma unroll
        for (int j = 0; j < 4; j++) {
#pragma unroll
            for (int e = 0; e < 4; e++) {
                int qg = (e < 2) ? qrow0 : qrow1;
                int kg = kt*32 + 8*j + 2*tg + (e & 1);
                float s = sfr[j][e] * 0.125f;
                if (kg >= kTA || (qg >= kPRE && kg > qg)) s = -INFINITY;
                sfr[j][e] = s;
            }
        }

        // ---- online softmax ----
        float mx0 = -INFINITY, mx1 = -INFINITY;
#pragma unroll
        for (int j = 0; j < 4; j++) {
            mx0 = fmaxf(mx0, fmaxf(sfr[j][0], sfr[j][1]));
            mx1 = fmaxf(mx1, fmaxf(sfr[j][2], sfr[j][3]));
        }
        mx0 = fmaxf(mx0, __shfl_xor_sync(0xffffffffu, mx0, 1));
        mx0 = fmaxf(mx0, __shfl_xor_sync(0xffffffffu, mx0, 2));
        mx1 = fmaxf(mx1, __shfl_xor_sync(0xffffffffu, mx1, 1));
        mx1 = fmaxf(mx1, __shfl_xor_sync(0xffffffffu, mx1, 2));
        float mn0 = fmaxf(mrow0, mx0), mn1 = fmaxf(mrow1, mx1);
        float corr0 = __expf(mrow0 - mn0), corr1 = __expf(mrow1 - mn1);

        float sum0 = 0.f, sum1 = 0.f;
        uint32_t ph[2][4], pl[2][4];
#pragma unroll
        for (int kc = 0; kc < 2; kc++) {
            float p00,p01,p02,p03, p10,p11,p12,p13;
            {
                int j = 2*kc;
                p00 = __expf(sfr[j][0] - mn0); p01 = __expf(sfr[j][1] - mn0);
                p02 = __expf(sfr[j][2] - mn1); p03 = __expf(sfr[j][3] - mn1);
                j = 2*kc + 1;
                p10 = __expf(sfr[j][0] - mn0); p11 = __expf(sfr[j][1] - mn0);
                p12 = __expf(sfr[j][2] - mn1); p13 = __expf(sfr[j][3] - mn1);
            }
            sum0 += p00 + p01 + p10 + p11;
            sum1 += p02 + p03 + p12 + p13;
            __nv_bfloat16 h0,l0,h1,l1;
            bsplit(p00,h0,l0); bsplit(p01,h1,l1);
            ph[kc][0] = packb(h0,h1); pl[kc][0] = packb(l0,l1);
            bsplit(p02,h0,l0); bsplit(p03,h1,l1);
            ph[kc][1] = packb(h0,h1); pl[kc][1] = packb(l0,l1);
            bsplit(p10,h0,l0); bsplit(p11,h1,l1);
            ph[kc][2] = packb(h0,h1); pl[kc][2] = packb(l0,l1);
            bsplit(p12,h0,l0); bsplit(p13,h1,l1);
            ph[kc][3] = packb(h0,h1); pl[kc][3] = packb(l0,l1);
        }
        sum0 += __shfl_xor_sync(0xffffffffu, sum0, 1);
        sum0 += __shfl_xor_sync(0xffffffffu, sum0, 2);
        sum1 += __shfl_xor_sync(0xffffffffu, sum1, 1);
        sum1 += __shfl_xor_sync(0xffffffffu, sum1, 2);
        lrow0 = lrow0*corr0 + sum0;
        lrow1 = lrow1*corr1 + sum1;
#pragma unroll
        for (int f = 0; f < 8; f++) {
            yacc[f][0] *= corr0; yacc[f][1] *= corr0;
            yacc[f][2] *= corr1; yacc[f][3] *= corr1;
        }
        mrow0 = mn0; mrow1 = mn1;

        // ---- y += P V ----
#pragma unroll
        for (int f = 0; f < 8; f++) {
            int dr = 8*f + gid;
#pragma unroll
            for (int kc = 0; kc < 2; kc++) {
                uint32_t vbh[2], vbl[2];
                vbh[0] = Vwh[dr*20 + 8*kc + tg];
                vbh[1] = Vwh[dr*20 + 8*kc + tg + 4];
                vbl[0] = Vwl[dr*20 + 8*kc + tg];
                vbl[1] = Vwl[dr*20 + 8*kc + tg + 4];
                mma_bf16(yacc[f], pl[kc], vbh);
                mma_bf16(yacc[f], ph[kc], vbl);
                mma_bf16(yacc[f], ph[kc], vbh);
            }
        }
    }

    // ---- write y (split planes) ----
    float inv0 = 1.f / lrow0, inv1 = 1.f / lrow1;
#pragma unroll
    for (int f = 0; f < 8; f++) {
        int d = hh*kDH + 8*f + 2*tg;
        if (qrow0 < kTA) {
            long a = ((long)(bb*kTA + qrow0))*kC + d;
            __nv_bfloat16 h0,l0,h1,l1;
            bsplit(yacc[f][0]*inv0, h0, l0); bsplit(yacc[f][1]*inv0, h1, l1);
            *(__nv_bfloat162*)&ys[a] = __nv_bfloat162{h0,h1};
            *(__nv_bfloat162*)&ys[planeN + a] = __nv_bfloat162{l0,l1};
        }
        if (qrow1 < kTA) {
            long a = ((long)(bb*kTA + qrow1))*kC + d;
            __nv_bfloat16 h0,l0,h1,l1;
            bsplit(yacc[f][2]*inv1, h0, l0); bsplit(yacc[f][3]*inv1, h1, l1);
            *(__nv_bfloat162*)&ys[a] = __nv_bfloat162{h0,h1};
            *(__nv_bfloat162*)&ys[planeN + a] = __nv_bfloat162{l0,l1};
        }
    }
}

// ---------------- layernorm (writes split planes) ----------------
__global__ __launch_bounds__(256)
void ln_k(const float* __restrict__ x, const float* __restrict__ w,
          const float* __restrict__ b, __nv_bfloat16* __restrict__ o, long planeN)
{
    const long row = blockIdx.x;
    const float* xr = x + row*kC;
    float s = 0.f, s2 = 0.f;
    for (int c = threadIdx.x; c < kC; c += 256) { float v = xr[c]; s += v; s2 += v*v; }
    __shared__ float sh[64];
#pragma unroll
    for (int off=16;off;off>>=1){ s += __shfl_xor_sync(0xffffffffu,s,off); s2 += __shfl_xor_sync(0xffffffffu,s2,off); }
    int wid = threadIdx.x >> 5, lane = threadIdx.x & 31;
    if (lane == 0){ sh[wid] = s; sh[32+wid] = s2; }
    __syncthreads();
    if (threadIdx.x < 32) {
        s  = (lane < 8) ? sh[lane]    : 0.f;
        s2 = (lane < 8) ? sh[32+lane] : 0.f;
#pragma unroll
        for (int off=4;off;off>>=1){ s += __shfl_xor_sync(0xffffffffu,s,off); s2 += __shfl_xor_sync(0xffffffffu,s2,off); }
        if (lane == 0){ sh[0] = s; sh[1] = s2; }
    }
    __syncthreads();
    float mean = sh[0] * (1.f/kC);
    float var  = sh[1] * (1.f/kC) - mean*mean;
    float rstd = rsqrtf(var + 1e-5f);
    for (int c = threadIdx.x; c < kC; c += 256) {
        float v = (xr[c]-mean)*rstd*w[c] + b[c];
        __nv_bfloat16 h,lo2; bsplit(v,h,lo2);
        o[row*kC + c] = h;
        o[planeN + row*kC + c] = lo2;
    }
}

// ---------------- small kernels ----------------
__global__ void pool_k(const float* __restrict__ mem, __nv_bfloat16* __restrict__ pooled, long planeN)
{
    const int bm = blockIdx.x;
    const int bI = bm / kM, mI = bm % kM;
    const int seg = kT / kM;
    const float* src = mem + ((long)bI*kT + (long)mI*seg)*kC;
    for (int c = threadIdx.x; c < kC; c += blockDim.x) {
        float s = 0.f;
        for (int t = 0; t < seg; t++) s += src[(long)t*kC + c];
        float v = s * (1.f/seg);
        __nv_bfloat16 h,l; bsplit(v,h,l);
        pooled[(long)bm*kC + c] = h;
        pooled[planeN + (long)bm*kC + c] = l;
    }
}

__global__ void concat_k(const float* __restrict__ retr, const float* __restrict__ pm,
                         const float* __restrict__ x, float* __restrict__ xa)
{
    long i = (long)blockIdx.x*blockDim.x + threadIdx.x;
    if (i >= (long)kB*kTA*kC) return;
    int c = (int)(i % kC); long r = i / kC; int t = (int)(r % kTA); int b = (int)(r / kTA);
    float v;
    if (t < kM)        v = retr[((long)b*kM + t)*kC + c];
    else if (t < kPRE) v = pm[(long)(t-kM)*kC + c];
    else               v = x[((long)b*kT + (t-kPRE))*kC + c];
    xa[i] = v;
}

__global__ void copyout_k(const float* __restrict__ xa2, float* __restrict__ out,
                          __nv_bfloat16* __restrict__ outs, long planeN)
{
    long i = (long)blockIdx.x*blockDim.x + threadIdx.x;
    if (i >= OUT_N) return;
    int c = (int)(i % kC); long r = i / kC; int t = (int)(r % kT); int b = (int)(r / kT);
    float v = xa2[((long)b*kTA + kPRE + t)*kC + c];
    out[i] = v;
    __nv_bfloat16 h,l; bsplit(v,h,l);
    outs[i] = h; outs[planeN + i] = l;
}

__global__ void silu_k(const float* __restrict__ z, float* __restrict__ o,
                       __nv_bfloat16* __restrict__ os, long planeN, long n)
{
    long i = (long)blockIdx.x*blockDim.x + threadIdx.x;
    if (i >= n) return;
    float v = z[i];
    float r = v / (1.f + __expf(-v));
    o[i] = r;
    __nv_bfloat16 h,l; bsplit(r,h,l);
    os[i] = h; os[planeN + i] = l;
}

__global__ void dpred_k(float* __restrict__ p, const float* __restrict__ v,
                        __nv_bfloat16* __restrict__ ps, long planeN, long n, float scale)
{
    long i = (long)blockIdx.x*blockDim.x + threadIdx.x;
    if (i >= n) return;
    float r = (p[i] - v[i]) * scale;
    p[i] = r;
    __nv_bfloat16 h,l; bsplit(r,h,l);
    ps[i] = h; ps[planeN + i] = l;
}

__global__ void dsilu_mul_k(float* __restrict__ dh, const float* __restrict__ z, long n)
{
    long i = (long)blockIdx.x*blockDim.x + threadIdx.x;
    if (i >= n) return;
    float zz = z[i];
    float sig = 1.f / (1.f + __expf(-zz));
    dh[i] *= sig * (1.f + zz*(1.f - sig));
}

__global__ void zero_k(float* __restrict__ a, long n)
{
    long i = (long)blockIdx.x*blockDim.x + threadIdx.x;
    if (i < n) a[i] = 0.f;
}

__global__ void colsum_k(const float* __restrict__ in, float* __restrict__ out,
                         int rows, int cols, int rowsPerSeg)
{
    int z = blockIdx.z;
    in  += (long)z*rows*cols;
    out += (long)z*cols;
    int j = blockIdx.x*blockDim.x + threadIdx.x;
    if (j >= cols) return;
    int t0 = blockIdx.y * rowsPerSeg;
    int t1 = t0 + rowsPerSeg; if (t1 > rows) t1 = rows;
    float s = 0.f;
    for (int t = t0; t < t1; t++) s += in[(long)t*cols + j];
    atomicAdd(out + j, s);
}

__global__ void update_k(const float* __restrict__ w, const float* __restrict__ mom,
                         const float* __restrict__ g, float* __restrict__ outW,
                         float* __restrict__ outM, long n)
{
    long i = (long)blockIdx.x*blockDim.x + threadIdx.x;
    if (i >= n) return;
    float nm = kMU*mom[i] + g[i];
    outM[i] = nm;
    outW[i] = (1.f - kDECAY)*w[i] - kLR*nm;
}

__global__ void split_k(const float* __restrict__ in, __nv_bfloat16* __restrict__ out, long n)
{
    long i = (long)blockIdx.x*blockDim.x + threadIdx.x;
    if (i >= n) return;
    __nv_bfloat16 h,l; bsplit(in[i],h,l);
    out[i] = h; out[n + i] = l;
}

__global__ void transpose_split_k(const float* __restrict__ in, __nv_bfloat16* __restrict__ out,
                                  long planeN, int rows, int cols)
{
    __shared__ float tile[32][33];
    long zoff = (long)blockIdx.z * rows * cols;
    int c0 = blockIdx.x*32, r0 = blockIdx.y*32;
    int tx = threadIdx.x, ty = threadIdx.y;
#pragma unroll
    for (int i = 0; i < 32; i += 8) {
        int r = r0 + ty + i, c = c0 + tx;
        if (r < rows && c < cols) tile[ty+i][tx] = in[zoff + (long)r*cols + c];
    }
    __syncthreads();
#pragma unroll
    for (int i = 0; i < 32; i += 8) {
        int r = c0 + ty + i, c = r0 + tx;
        if (r < cols && c < rows) {
            __nv_bfloat16 h,l; bsplit(tile[tx][ty+i],h,l);
            out[zoff + (long)r*rows + c] = h;
            out[planeN + zoff + (long)r*rows + c] = l;
        }
    }
}

// ---------------- host side ----------------
template<int EPI, bool WF32, bool WSPLIT>
static void bgemm(const __nv_bfloat16* A, long aPlane, long sA,
                  const __nv_bfloat16* B, long bPlane, long sB,
                  const float* bias, long sBias, const float* res, long sRes,
                  float* C, __nv_bfloat16* Cs, long cPlane, long sC,
                  int M, int N, int K, int batch)
{
    cudaFuncSetAttribute(bgemm_k<EPI,WF32,WSPLIT>,
                         cudaFuncAttributeMaxDynamicSharedMemorySize, MSMEM);
    dim3 grid(N/MBN, (M + MBM - 1)/MBM, batch);
    bgemm_k<EPI,WF32,WSPLIT><<<grid, 256, MSMEM>>>(A, B, bias, res, C, Cs,
        M, N, K, aPlane, bPlane, cPlane, sA, sB, sBias, sRes, sC);
}

static inline long cdiv(long a, long b){ return (a + b - 1)/b; }

#define GETF(var, sym) float* var; { void* _p=nullptr; cudaGetSymbolAddress(&_p, sym); var=(float*)_p; }
#define GETB(var, sym) __nv_bfloat16* var; { void* _p=nullptr; cudaGetSymbolAddress(&_p, sym); var=(__nv_bfloat16*)_p; }

extern "C" void kernel_launch(void* const* d_in, const int* in_sizes, int n_in,
                              void* d_out, int out_size)
{
    const float* x       = (const float*)d_in[0];
    const float* persist = (const float*)d_in[1];
    const float* ln1w    = (const float*)d_in[2];
    const float* ln1b    = (const float*)d_in[3];
    const float* ln2w    = (const float*)d_in[4];
    const float* ln2b    = (const float*)d_in[5];
    const float* attnw   = (const float*)d_in[6];
    const float* attnb   = (const float*)d_in[7];
    const float* projw   = (const float*)d_in[8];
    const float* projb   = (const float*)d_in[9];
    const float* fcw     = (const float*)d_in[10];
    const float* fcb     = (const float*)d_in[11];
    const float* mlpw    = (const float*)d_in[12];
    const float* mlpb    = (const float*)d_in[13];
    const float* qw      = (const float*)d_in[14];
    const float* qb      = (const float*)d_in[15];
    const float* kw      = (const float*)d_in[16];
    const float* kb      = (const float*)d_in[17];
    const float* vw      = (const float*)d_in[18];
    const float* vb      = (const float*)d_in[19];
    const float* ow      = (const float*)d_in[20];
    const float* ob      = (const float*)d_in[21];
    const float* memw0   = (const float*)d_in[22];
    const float* memb0   = (const float*)d_in[23];
    const float* memw1   = (const float*)d_in[24];
    const float* memb1   = (const float*)d_in[25];
    const float* momw0   = (const float*)d_in[26];
    const float* momb0   = (const float*)d_in[27];
    const float* momw1   = (const float*)d_in[28];
    const float* momb1   = (const float*)d_in[29];
    float* out = (float*)d_out;

    GETF(zbuf, g_h);    GETF(hh, g_hh);    GETF(memb, g_mem);  GETF(retr, g_retr);
    GETF(xa, g_xa);     GETF(qkv, g_qkv);  GETF(xa2, g_xa2);   GETF(keys, g_keys);
    GETF(vals, g_vals); GETF(dh, g_dh);    GETF(gw0, g_gw0);   GETF(gw1, g_gw1);
    GETF(gb0, g_gb0);   GETF(gb1, g_gb1);

    GETB(px,    s_x);     GETB(pq,    s_q);     GETB(ph,    s_h);     GETB(ppool, s_pool);
    GETB(phln,  s_hln);   GETB(py,    s_y);     GETB(phfc,  s_hfc);   GETB(pout,  s_out);
    GETB(pkeys, s_keys);  GETB(phh,   s_hh);    GETB(pdp,   s_dp);    GETB(pdpT,  s_dpT);
    GETB(phhT,  s_hhT);   GETB(pdzT,  s_dzT);   GETB(pkeysT,s_keysT); GETB(pw1T,  s_w1T);
    GETB(pqw,   s_qw);    GETB(pkw,   s_kw);    GETB(pvw,   s_vw);    GETB(pow_,  s_ow);
    GETB(pprojw,s_projw); GETB(pattnw,s_attnw); GETB(pfcw,  s_fcw);   GETB(pmlpw, s_mlpw);
    GETB(pw0,   s_w0);    GETB(pw1,   s_w1);

    const long sTC = (long)kT*kC, sTH = (long)kT*kHID;
    const long sW0 = (long)kHID*kC, sW1 = (long)kC*kHID;

    auto split = [&](const float* in, __nv_bfloat16* outp, long n){
        split_k<<<(unsigned)cdiv(n,256),256>>>(in, outp, n);
    };
    split(x, px, N_X);
    split(qw, pqw, N_SQW);   split(kw, pkw, N_SQW);   split(vw, pvw, N_SQW);
    split(ow, pow_, N_SQW);  split(projw, pprojw, N_SQW);
    split(attnw, pattnw, N_ATTNW);
    split(fcw, pfcw, N_FCW); split(mlpw, pmlpw, N_MLPW);
    split(memw0, pw0, N_W0); split(memw1, pw1, N_W1);
    transpose_split_k<<<dim3(kHID/32, kC/32, kB), dim3(32,8)>>>(memw1, pw1T, N_W1T, kC, kHID);

    // --- forward memory read path ---
    bgemm<EP_NONE,false,true>(px,N_X,0, pqw,N_SQW,0, qb,0, nullptr,0,
                              nullptr, pq,N_Q, 0, kB*kT, kC, kC, 1);
    bgemm<EP_SILU,false,true>(pq,N_Q,sTC, pw0,N_W0,sW0, memb0,kHID, nullptr,0,
                              nullptr, ph,N_H, sTH, kT, kHID, kC, kB);
    bgemm<EP_NONE,true,false>(ph,N_H,sTH, pw1,N_W1,sW1, memb1,kC, nullptr,0,
                              memb, nullptr,0, sTC, kT, kC, kHID, kB);
    pool_k<<<kB*kM, 256>>>(memb, ppool, N_POOL);
    bgemm<EP_NONE,true,false>(ppool,N_POOL,0, pow_,N_SQW,0, ob,0, nullptr,0,
                              retr, nullptr,0, 0, kB*kM, kC, kC, 1);
    {
        long n = (long)kB*kTA*kC;
        concat_k<<<(unsigned)cdiv(n,256),256>>>(retr, persist, x, xa);
    }

    // --- transformer block ---
    ln_k<<<kB*kTA,256>>>(xa, ln1w, ln1b, phln, N_HLN);
    bgemm<EP_NONE,true,false>(phln,N_HLN,0, pattnw,N_ATTNW,0, attnb,0, nullptr,0,
                              qkv, nullptr,0, 0, kB*kTA, 3*kC, kC, 1);
    attn_mma_k<<<dim3((kTA+63)/64, kB*kH), 128>>>(qkv, py, N_Y);
    bgemm<EP_NONE,true,false>(py,N_Y,0, pprojw,N_SQW,0, projb,0, xa,0,
                              xa2, nullptr,0, 0, kB*kTA, kC, kC, 1);
    ln_k<<<kB*kTA,256>>>(xa2, ln2w, ln2b, phln, N_HLN);
    bgemm<EP_GELU,false,true>(phln,N_HLN,0, pfcw,N_FCW,0, fcb,0, nullptr,0,
                              nullptr, phfc,N_HFC, 0, kB*kTA, 4*kC, kC, 1);
    bgemm<EP_NONE,true,false>(phfc,N_HFC,0, pmlpw,N_MLPW,0, mlpb,0, xa2,0,
                              xa2, nullptr,0, 0, kB*kTA, kC, 4*kC, 1);
    copyout_k<<<(unsigned)cdiv(OUT_N,256),256>>>(xa2, out, pout, N_OUT);

    // --- memory write path ---
    bgemm<EP_NONE,true,true>(pout,N_OUT,0, pkw,N_SQW,0, kb,0, nullptr,0,
                             keys, pkeys,N_KEYS, 0, kB*kT, kC, kC, 1);
    bgemm<EP_NONE,true,false>(pout,N_OUT,0, pvw,N_SQW,0, vb,0, nullptr,0,
                              vals, nullptr,0, 0, kB*kT, kC, kC, 1);
    bgemm<EP_NONE,true,false>(pkeys,N_KEYS,sTC, pw0,N_W0,sW0, memb0,kHID, nullptr,0,
                              zbuf, nullptr,0, sTH, kT, kHID, kC, kB);
    {
        long n = (long)kB*kT*kHID;
        silu_k<<<(unsigned)cdiv(n,256),256>>>(zbuf, hh, phh, N_HH, n);
    }
    bgemm<EP_NONE,true,false>(phh,N_HH,sTH, pw1,N_W1,sW1, memb1,kC, nullptr,0,
                              memb, nullptr,0, sTC, kT, kC, kHID, kB);
    {
        long n = (long)kB*kT*kC;
        dpred_k<<<(unsigned)cdiv(n,256),256>>>(memb, vals, pdp, N_DP, n, 2.f/((float)kT*(float)kC));
    }
    zero_k<<<(unsigned)cdiv(B0_N,256),256>>>(gb0, B0_N);
    zero_k<<<(unsigned)cdiv(B1_N,256),256>>>(gb1, B1_N);
    colsum_k<<<dim3((kC+255)/256, 8, kB),256>>>(memb, gb1, kT, kC, kT/8);

    transpose_split_k<<<dim3(kC/32,  kT/32, kB), dim3(32,8)>>>(memb, pdpT, N_DPT, kT, kC);
    transpose_split_k<<<dim3(kHID/32,kT/32, kB), dim3(32,8)>>>(hh,   phhT, N_HHT, kT, kHID);

    bgemm<EP_NONE,true,false>(pdpT,N_DPT,sTC, phhT,N_HHT,sTH, nullptr,0, nullptr,0,
                              gw1, nullptr,0, sW1, kC, kHID, kT, kB);
    bgemm<EP_NONE,true,false>(pdp,N_DP,sTC, pw1T,N_W1T,sW0, nullptr,0, nullptr,0,
                              dh, nullptr,0, sTH, kT, kHID, kC, kB);
    {
        long n = (long)kB*kT*kHID;
        dsilu_mul_k<<<(unsigned)cdiv(n,256),256>>>(dh, zbuf, n);
    }
    colsum_k<<<dim3((kHID+255)/256, 8, kB),256>>>(dh, gb0, kT, kHID, kT/8);
    transpose_split_k<<<dim3(kHID/32,kT/32, kB), dim3(32,8)>>>(dh,   pdzT,  N_DZT,  kT, kHID);
    transpose_split_k<<<dim3(kC/32,  kT/32, kB), dim3(32,8)>>>(keys, pkeysT,N_KEYST,kT, kC);
    bgemm<EP_NONE,true,false>(pdzT,N_DZT,sTH, pkeysT,N_KEYST,sTC, nullptr,0, nullptr,0,
                              gw0, nullptr,0, sW0, kHID, kC, kT, kB);

    // --- updates into output tuple ---
    update_k<<<(unsigned)cdiv(W0_N,256),256>>>(memw0, momw0, gw0, out+OFF_NW0, out+OFF_NMW0, W0_N);
    update_k<<<(unsigned)cdiv(B0_N,256),256>>>(memb0, momb0, gb0, out+OFF_NB0, out+OFF_NMB0, B0_N);
    update_k<<<(unsigned)cdiv(W1_N,256),256>>>(memw1, momw1, gw1, out+OFF_NW1, out+OFF_NMW1, W1_N);
    update_k<<<(unsigned)cdiv(B1_N,256),256>>>(memb1, momb1, gb1, out+OFF_NB1, out+OFF_NMB1, B1_N);

    (void)in_sizes; (void)n_in; (void)out_size;
}

// round 8
// speedup vs baseline: 3.3655x; 1.1071x over previous
#include <cuda_runtime.h>
#include <cuda_bf16.h>
#include <math.h>
#include <stdint.h>

// ---------------- problem constants ----------------
constexpr int kB   = 8;
constexpr int kT   = 1024;
constexpr int kC   = 768;
constexpr int kH   = 12;
constexpr int kDH  = 64;
constexpr int kHID = 1536;   // 2*C
constexpr int kM   = 16;
constexpr int kP   = 4;
constexpr int kPRE = kM + kP;      // 20
constexpr int kTA  = kT + kPRE;    // 1044
constexpr float kLR = 0.01f, kMU = 0.9f, kDECAY = 0.001f;

constexpr long OUT_N = (long)kB*kT*kC;
constexpr long W0_N  = (long)kB*kHID*kC;
constexpr long B0_N  = (long)kB*kHID;
constexpr long W1_N  = (long)kB*kC*kHID;
constexpr long B1_N  = (long)kB*kC;
constexpr long OFF_NW0  = OUT_N;
constexpr long OFF_NB0  = OFF_NW0  + W0_N;
constexpr long OFF_NW1  = OFF_NB0  + B0_N;
constexpr long OFF_NB1  = OFF_NW1  + W1_N;
constexpr long OFF_NMW0 = OFF_NB1  + B1_N;
constexpr long OFF_NMB0 = OFF_NMW0 + W0_N;
constexpr long OFF_NMW1 = OFF_NMB0 + B0_N;
constexpr long OFF_NMB1 = OFF_NMW1 + W1_N;

// ---------------- f32 scratch ----------------
__device__ float g_h    [(long)kB*kT*kHID];   // z (bw)
__device__ float g_hh   [(long)kB*kT*kHID];
__device__ float g_mem  [(long)kB*kT*kC];     // mem fwd / pred / dpred
__device__ float g_retr [(long)kB*kM*kC];
__device__ float g_xa   [(long)kB*kTA*kC];
__device__ float g_xa2  [(long)kB*kTA*kC];
__device__ float g_keys [(long)kB*kT*kC];
__device__ float g_vals [(long)kB*kT*kC];
__device__ float g_dh   [(long)kB*kT*kHID];
__device__ float g_gw0  [(long)kB*kHID*kC];
__device__ float g_gw1  [(long)kB*kC*kHID];
__device__ float g_gb0  [(long)kB*kHID];
__device__ float g_gb1  [(long)kB*kC];

// ---------------- bf16 split planes (size 2*N each: [hi | lo]) ----------------
constexpr long N_X     = (long)kB*kT*kC;
constexpr long N_Q     = N_X;
constexpr long N_H     = (long)kB*kT*kHID;
constexpr long N_POOL  = (long)kB*kM*kC;
constexpr long N_HLN   = (long)kB*kTA*kC;
constexpr long N_QKV   = (long)kB*kTA*3*kC;
constexpr long N_Y     = N_HLN;
constexpr long N_HFC   = (long)kB*kTA*4*kC;
constexpr long N_OUT   = N_X;
constexpr long N_KEYS  = N_X;
constexpr long N_HH    = N_H;
constexpr long N_DP    = N_X;
constexpr long N_DPT   = N_X;
constexpr long N_HHT   = N_H;
constexpr long N_DZT   = N_H;
constexpr long N_KEYST = N_X;
constexpr long N_W1T   = (long)kB*kHID*kC;
constexpr long N_SQW   = (long)kC*kC;
constexpr long N_ATTNW = (long)3*kC*kC;
constexpr long N_FCW   = (long)4*kC*kC;
constexpr long N_MLPW  = (long)4*kC*kC;
constexpr long N_W0    = (long)kB*kHID*kC;
constexpr long N_W1    = (long)kB*kC*kHID;

__device__ __nv_bfloat16 s_x    [2*N_X];
__device__ __nv_bfloat16 s_q    [2*N_Q];
__device__ __nv_bfloat16 s_h    [2*N_H];
__device__ __nv_bfloat16 s_pool [2*N_POOL];
__device__ __nv_bfloat16 s_hln  [2*N_HLN];
__device__ __nv_bfloat16 s_qkv  [2*N_QKV];
__device__ __nv_bfloat16 s_y    [2*N_Y];
__device__ __nv_bfloat16 s_hfc  [2*N_HFC];
__device__ __nv_bfloat16 s_out  [2*N_OUT];
__device__ __nv_bfloat16 s_keys [2*N_KEYS];
__device__ __nv_bfloat16 s_hh   [2*N_HH];
__device__ __nv_bfloat16 s_dp   [2*N_DP];
__device__ __nv_bfloat16 s_dpT  [2*N_DPT];
__device__ __nv_bfloat16 s_hhT  [2*N_HHT];
__device__ __nv_bfloat16 s_dzT  [2*N_DZT];
__device__ __nv_bfloat16 s_keysT[2*N_KEYST];
__device__ __nv_bfloat16 s_w1T  [2*N_W1T];
__device__ __nv_bfloat16 s_qw   [2*N_SQW];
__device__ __nv_bfloat16 s_kw   [2*N_SQW];
__device__ __nv_bfloat16 s_vw   [2*N_SQW];
__device__ __nv_bfloat16 s_ow   [2*N_SQW];
__device__ __nv_bfloat16 s_projw[2*N_SQW];
__device__ __nv_bfloat16 s_attnw[2*N_ATTNW];
__device__ __nv_bfloat16 s_fcw  [2*N_FCW];
__device__ __nv_bfloat16 s_mlpw [2*N_MLPW];
__device__ __nv_bfloat16 s_w0   [2*N_W0];
__device__ __nv_bfloat16 s_w1   [2*N_W1];

// ---------------- helpers ----------------
__device__ __forceinline__ uint32_t smem_u32(const void* p) {
    uint32_t a;
    asm("{ .reg .u64 t; cvta.to.shared.u64 t, %1; cvt.u32.u64 %0, t; }" : "=r"(a) : "l"(p));
    return a;
}

__device__ __forceinline__ void bsplit(float v, __nv_bfloat16& h, __nv_bfloat16& l) {
    h = __float2bfloat16(v);
    l = __float2bfloat16(v - __bfloat162float(h));
}

__device__ __forceinline__ uint32_t packb(__nv_bfloat16 a, __nv_bfloat16 b) {
    __nv_bfloat162 t; t.x = a; t.y = b;
    return *(uint32_t*)&t;
}

__device__ __forceinline__ void mma_bf16(float* d, const uint32_t* a, const uint32_t* b) {
    asm volatile(
        "mma.sync.aligned.m16n8k16.row.col.f32.bf16.bf16.f32 "
        "{%0,%1,%2,%3}, {%4,%5,%6,%7}, {%8,%9}, {%0,%1,%2,%3};"
        : "+f"(d[0]), "+f"(d[1]), "+f"(d[2]), "+f"(d[3])
        : "r"(a[0]), "r"(a[1]), "r"(a[2]), "r"(a[3]), "r"(b[0]), "r"(b[1]));
}

__device__ __forceinline__ void ldsm4(uint32_t* r, uint32_t addr) {
    asm volatile("ldmatrix.sync.aligned.m8n8.x4.shared.b16 {%0,%1,%2,%3}, [%4];"
        : "=r"(r[0]), "=r"(r[1]), "=r"(r[2]), "=r"(r[3]) : "r"(addr));
}

// ---------------- bf16-split GEMM (NT: A[M,K], B[N,K], K-major, pre-split hi/lo) ----------------
constexpr int MBM = 128, MBN = 128, MBK = 16, MSTG = 3;
constexpr int STG_WORDS = 4096;                    // 4 planes * 1024 words
constexpr unsigned MSMEM = MSTG * STG_WORDS * 4;   // 49152

enum { EP_NONE=0, EP_SILU=1, EP_GELU=2, EP_DSILU=3 };

template<int EPI, bool WF32, bool WSPLIT>
__global__ __launch_bounds__(256)
void bgemm_k(const __nv_bfloat16* __restrict__ A, const __nv_bfloat16* __restrict__ B,
             const float* __restrict__ bias, const float* __restrict__ res,
             float* __restrict__ C, __nv_bfloat16* __restrict__ Cs,
             int M, int N, int K,
             long aPlane, long bPlane, long cPlane,
             long sA, long sB, long sBias, long sRes, long sC)
{
    extern __shared__ float smf[];
    const uint32_t smb = smem_u32(smf);

    const int tid = threadIdx.x, lane = tid & 31, wid = tid >> 5;
    const int gid = lane >> 2, tg = lane & 3;
    const int wm = wid & 3, wn = wid >> 2;
    const int bz = blockIdx.z;
    const int m0 = blockIdx.y * MBM, n0 = blockIdx.x * MBN;
    const int nk = K / MBK;
    const int lq = lane >> 3, lsub = lane & 7;   // ldmatrix lane decomposition

    float acc[2][8][4];
#pragma unroll
    for (int i=0;i<2;i++)
#pragma unroll
        for (int j=0;j<8;j++)
#pragma unroll
            for (int r=0;r<4;r++) acc[i][j][r] = 0.f;

    auto load_stage = [&](int stage, int kt) {
        const int sw = stage * STG_WORDS;
#pragma unroll
        for (int it=0; it<4; it++) {
            int id = tid + it*256;
            int p = id >> 8;            // 0 Ahi, 1 Alo, 2 Bhi, 3 Blo
            int c = id & 255;
            int row = c >> 1, half = c & 1;
            const __nv_bfloat16* src;
            int sz = 16;
            if (p < 2) {
                int gm = m0 + row;
                int ok = gm < M;
                sz = ok ? 16 : 0;
                src = A + (p==1 ? aPlane : 0) + (long)bz*sA
                        + (long)(ok ? gm : 0)*K + kt*MBK + half*8;
            } else {
                src = B + (p==3 ? bPlane : 0) + (long)bz*sB
                        + (long)(n0 + row)*K + kt*MBK + half*8;
            }
            uint32_t dst = smb + (uint32_t)(sw + p*1024 + row*8
                              + ((half*4) ^ (((row>>2)&1)<<2)))*4u;
            asm volatile("cp.async.cg.shared.global [%0], [%1], 16, %2;\n"
                         :: "r"(dst), "l"(src), "r"(sz));
        }
        asm volatile("cp.async.commit_group;\n");
    };

    auto compute = [&](int stage) {
        const uint32_t sbase = smb + (uint32_t)stage * STG_WORDS * 4u;
        uint32_t ahi[2][4], alo[2][4];
        // A fragments: matrices ordered (mlow,klow),(mhigh,klow),(mlow,khigh),(mhigh,khigh)
#pragma unroll
        for (int i=0;i<2;i++) {
            int row = wm*32 + i*16 + lsub + (lq & 1)*8;
            uint32_t off = (uint32_t)(row*32 + (((lq>>1)*16) ^ ((row & 4) << 2)));
            ldsm4(ahi[i], sbase + off);
            ldsm4(alo[i], sbase + 4096u + off);
        }
#pragma unroll
        for (int jp=0;jp<4;jp++) {
            // B pair (j=2jp, 2jp+1): matrices (j,klow),(j,khigh),(j+1,klow),(j+1,khigh)
            int rowb = wn*64 + jp*16 + (lq>>1)*8 + lsub;
            uint32_t offb = (uint32_t)(rowb*32 + (((lq&1)*16) ^ ((rowb & 4) << 2)));
            uint32_t bh[4], bl[4];
            ldsm4(bh, sbase + 8192u  + offb);
            ldsm4(bl, sbase + 12288u + offb);
#pragma unroll
            for (int i=0;i<2;i++) {
                mma_bf16(acc[i][2*jp],   alo[i], bh);
                mma_bf16(acc[i][2*jp],   ahi[i], bl);
                mma_bf16(acc[i][2*jp],   ahi[i], bh);
                mma_bf16(acc[i][2*jp+1], alo[i], bh+2);
                mma_bf16(acc[i][2*jp+1], ahi[i], bl+2);
                mma_bf16(acc[i][2*jp+1], ahi[i], bh+2);
            }
        }
    };

    load_stage(0, 0);
    if (nk > 1) load_stage(1, 1);
    for (int kt = 0; kt < nk; kt++) {
        if (kt + 1 < nk) asm volatile("cp.async.wait_group 1;\n");
        else             asm volatile("cp.async.wait_group 0;\n");
        __syncthreads();
        compute(kt % MSTG);
        if (kt + 2 < nk) load_stage((kt + 2) % MSTG, kt + 2);
        __syncthreads();
    }

    const float* bp = bias ? bias + (long)bz*sBias : nullptr;
#pragma unroll
    for (int i=0;i<2;i++) {
#pragma unroll
        for (int half=0; half<2; half++) {
            int row = m0 + wm*32 + i*16 + gid + half*8;
            if (row >= M) continue;
            long rbase = (long)bz*sC + (long)row*N;
#pragma unroll
            for (int j=0;j<8;j++) {
                int col = n0 + wn*64 + j*8 + tg*2;
                float v0 = acc[i][j][half*2+0];
                float v1 = acc[i][j][half*2+1];
                if (bp) { v0 += bp[col]; v1 += bp[col+1]; }
                if (EPI == EP_SILU) {
                    v0 = v0 / (1.f + __expf(-v0));
                    v1 = v1 / (1.f + __expf(-v1));
                }
                if (EPI == EP_GELU) {
                    v0 = 0.5f*v0*(1.f + erff(v0*0.70710678118654752f));
                    v1 = 0.5f*v1*(1.f + erff(v1*0.70710678118654752f));
                }
                if (EPI == EP_DSILU) {
                    const float* zr = res + (long)bz*sRes + (long)row*N;
                    float z0 = zr[col], z1 = zr[col+1];
                    float s0 = 1.f/(1.f + __expf(-z0));
                    float s1 = 1.f/(1.f + __expf(-z1));
                    v0 *= s0*(1.f + z0*(1.f - s0));
                    v1 *= s1*(1.f + z1*(1.f - s1));
                }
                if (res && EPI != EP_DSILU) {
                    const float* rrow = res + (long)bz*sRes + (long)row*N;
                    v0 += rrow[col]; v1 += rrow[col+1];
                }
                if (WF32) {
                    float2 o; o.x = v0; o.y = v1;
                    *(float2*)(C + rbase + col) = o;
                }
                if (WSPLIT) {
                    __nv_bfloat16 h0,l0,h1,l1;
                    bsplit(v0, h0, l0); bsplit(v1, h1, l1);
                    *(__nv_bfloat162*)(Cs + rbase + col) = __nv_bfloat162{h0,h1};
                    *(__nv_bfloat162*)(Cs + cPlane + rbase + col) = __nv_bfloat162{l0,l1};
                }
            }
        }
    }
}

// ---------------- mma flash attention (split-bf16 qkv input) ----------------
__global__ __launch_bounds__(128)
void attn_mma_k(const __nv_bfloat16* __restrict__ qkvs, long qkvPlane,
                __nv_bfloat16* __restrict__ ys, long planeN)
{
    __shared__ __nv_bfloat16 Qh[64*72], Ql[64*72];
    __shared__ __nv_bfloat16 Kh[32*72], Kl[32*72];
    __shared__ __nv_bfloat16 Vh[64*40], Vl[64*40];

    const int bh = blockIdx.y;
    const int bb = bh / kH, hh = bh % kH;
    const int q0 = blockIdx.x * 64;
    const int tid = threadIdx.x, lane = tid & 31, wq = tid >> 5;
    const int gid = lane >> 2, tg = lane & 3;

    const __nv_bfloat16* qhiP = qkvs;
    const __nv_bfloat16* qloP = qkvs + qkvPlane;

    uint32_t* QwhW = (uint32_t*)Qh;  uint32_t* QwlW = (uint32_t*)Ql;
    uint32_t* KwhW = (uint32_t*)Kh;  uint32_t* KwlW = (uint32_t*)Kl;
    const uint32_t* Qwh = (const uint32_t*)Qh;
    const uint32_t* Qwl = (const uint32_t*)Ql;
    const uint32_t* Kwh = (const uint32_t*)Kh;
    const uint32_t* Kwl = (const uint32_t*)Kl;
    const uint32_t* Vwh = (const uint32_t*)Vh;
    const uint32_t* Vwl = (const uint32_t*)Vl;

    // ---- load Q tile (64 rows x 32 words) ----
#pragma unroll
    for (int it = 0; it < 16; it++) {
        int idx = tid + it*128;
        int row = idx >> 5, w = idx & 31;
        int qg = q0 + row;
        uint32_t vh = 0, vl = 0;
        if (qg < kTA) {
            long base = ((long)(bb*kTA + qg))*3*kC + hh*kDH + 2*w;
            vh = *(const uint32_t*)&qhiP[base];
            vl = *(const uint32_t*)&qloP[base];
        }
        QwhW[row*36 + w] = vh;
        QwlW[row*36 + w] = vl;
    }
    __syncthreads();

    // ---- Q fragments ----
    uint32_t qh[4][4], ql[4][4];
    {
        int r0 = wq*16 + gid;
#pragma unroll
        for (int c = 0; c < 4; c++) {
            qh[c][0] = Qwh[ r0    *36 + 8*c + tg];
            qh[c][1] = Qwh[(r0+8) *36 + 8*c + tg];
            qh[c][2] = Qwh[ r0    *36 + 8*c + tg + 4];
            qh[c][3] = Qwh[(r0+8) *36 + 8*c + tg + 4];
            ql[c][0] = Qwl[ r0    *36 + 8*c + tg];
            ql[c][1] = Qwl[(r0+8) *36 + 8*c + tg];
            ql[c][2] = Qwl[ r0    *36 + 8*c + tg + 4];
            ql[c][3] = Qwl[(r0+8) *36 + 8*c + tg + 4];
        }
    }

    float yacc[8][4];
#pragma unroll
    for (int f=0; f<8; f++)
#pragma unroll
        for (int e=0; e<4; e++) yacc[f][e] = 0.f;
    float mrow0 = -INFINITY, mrow1 = -INFINITY, lrow0 = 0.f, lrow1 = 0.f;

    const int qrow0 = q0 + wq*16 + gid;
    const int qrow1 = qrow0 + 8;

    int ntiles = (q0 == 0) ? (kTA + 31)/32 : (q0/32 + 2);
    if (ntiles > (kTA + 31)/32) ntiles = (kTA + 31)/32;

    for (int kt = 0; kt < ntiles; kt++) {
        __syncthreads();
        // ---- K tile (32 x 32 words) ----
#pragma unroll
        for (int it = 0; it < 8; it++) {
            int idx = tid + it*128;
            int row = idx >> 5, w = idx & 31;
            int kg = kt*32 + row;
            uint32_t vh = 0, vl = 0;
            if (kg < kTA) {
                long base = ((long)(bb*kTA + kg))*3*kC + kC + hh*kDH + 2*w;
                vh = *(const uint32_t*)&qhiP[base];
                vl = *(const uint32_t*)&qloP[base];
            }
            KwhW[row*36 + w] = vh;
            KwlW[row*36 + w] = vl;
        }
        // ---- V tile transposed ----
#pragma unroll
        for (int it = 0; it < 8; it++) {
            int idx = tid + it*128;
            int row = idx >> 5, w = idx & 31;
            int kg = kt*32 + row;
            uint32_t vh = 0, vl = 0;
            if (kg < kTA) {
                long base = ((long)(bb*kTA + kg))*3*kC + 2*kC + hh*kDH + 2*w;
                vh = *(const uint32_t*)&qhiP[base];
                vl = *(const uint32_t*)&qloP[base];
            }
            __nv_bfloat162 h2 = *(__nv_bfloat162*)&vh;
            __nv_bfloat162 l2 = *(__nv_bfloat162*)&vl;
            Vh[(2*w)*40 + row]   = h2.x;
            Vh[(2*w+1)*40 + row] = h2.y;
            Vl[(2*w)*40 + row]   = l2.x;
            Vl[(2*w+1)*40 + row] = l2.y;
        }
        __syncthreads();

        // ---- S = Q K^T ----
        float sfr[4][4];
#pragma unroll
        for (int j=0;j<4;j++)
#pragma unroll
            for (int e=0;e<4;e++) sfr[j][e] = 0.f;
#pragma unroll
        for (int j = 0; j < 4; j++) {
            int kr = 8*j + gid;
#pragma unroll
            for (int c = 0; c < 4; c++) {
                uint32_t kbh[2], kbl[2];
                kbh[0] = Kwh[kr*36 + 8*c + tg];
                kbh[1] = Kwh[kr*36 + 8*c + tg + 4];
                kbl[0] = Kwl[kr*36 + 8*c + tg];
                kbl[1] = Kwl[kr*36 + 8*c + tg + 4];
                mma_bf16(sfr[j], ql[c], kbh);
                mma_bf16(sfr[j], qh[c], kbl);
                mma_bf16(sfr[j], qh[c], kbh);
            }
        }

        // ---- scale + mask ----
#pragma unroll
        for (int j = 0; j < 4; j++) {
#pragma unroll
            for (int e = 0; e < 4; e++) {
                int qg = (e < 2) ? qrow0 : qrow1;
                int kg = kt*32 + 8*j + 2*tg + (e & 1);
                float s = sfr[j][e] * 0.125f;
                if (kg >= kTA || (qg >= kPRE && kg > qg)) s = -INFINITY;
                sfr[j][e] = s;
            }
        }

        // ---- online softmax ----
        float mx0 = -INFINITY, mx1 = -INFINITY;
#pragma unroll
        for (int j = 0; j < 4; j++) {
            mx0 = fmaxf(mx0, fmaxf(sfr[j][0], sfr[j][1]));
            mx1 = fmaxf(mx1, fmaxf(sfr[j][2], sfr[j][3]));
        }
        mx0 = fmaxf(mx0, __shfl_xor_sync(0xffffffffu, mx0, 1));
        mx0 = fmaxf(mx0, __shfl_xor_sync(0xffffffffu, mx0, 2));
        mx1 = fmaxf(mx1, __shfl_xor_sync(0xffffffffu, mx1, 1));
        mx1 = fmaxf(mx1, __shfl_xor_sync(0xffffffffu, mx1, 2));
        float mn0 = fmaxf(mrow0, mx0), mn1 = fmaxf(mrow1, mx1);
        float corr0 = __expf(mrow0 - mn0), corr1 = __expf(mrow1 - mn1);

        float sum0 = 0.f, sum1 = 0.f;
        uint32_t ph[2][4], pl[2][4];
#pragma unroll
        for (int kc = 0; kc < 2; kc++) {
            float p00,p01,p02,p03, p10,p11,p12,p13;
            {
                int j = 2*kc;
                p00 = __expf(sfr[j][0] - mn0); p01 = __expf(sfr[j][1] - mn0);
                p02 = __expf(sfr[j][2] - mn1); p03 = __expf(sfr[j][3] - mn1);
                j = 2*kc + 1;
                p10 = __expf(sfr[j][0] - mn0); p11 = __expf(sfr[j][1] - mn0);
                p12 = __expf(sfr[j][2] - mn1); p13 = __expf(sfr[j][3] - mn1);
            }
            sum0 += p00 + p01 + p10 + p11;
            sum1 += p02 + p03 + p12 + p13;
            __nv_bfloat16 h0,l0,h1,l1;
            bsplit(p00,h0,l0); bsplit(p01,h1,l1);
            ph[kc][0] = packb(h0,h1); pl[kc][0] = packb(l0,l1);
            bsplit(p02,h0,l0); bsplit(p03,h1,l1);
            ph[kc][1] = packb(h0,h1); pl[kc][1] = packb(l0,l1);
            bsplit(p10,h0,l0); bsplit(p11,h1,l1);
            ph[kc][2] = packb(h0,h1); pl[kc][2] = packb(l0,l1);
            bsplit(p12,h0,l0); bsplit(p13,h1,l1);
            ph[kc][3] = packb(h0,h1); pl[kc][3] = packb(l0,l1);
        }
        sum0 += __shfl_xor_sync(0xffffffffu, sum0, 1);
        sum0 += __shfl_xor_sync(0xffffffffu, sum0, 2);
        sum1 += __shfl_xor_sync(0xffffffffu, sum1, 1);
        sum1 += __shfl_xor_sync(0xffffffffu, sum1, 2);
        lrow0 = lrow0*corr0 + sum0;
        lrow1 = lrow1*corr1 + sum1;
#pragma unroll
        for (int f = 0; f < 8; f++) {
            yacc[f][0] *= corr0; yacc[f][1] *= corr0;
            yacc[f][2] *= corr1; yacc[f][3] *= corr1;
        }
        mrow0 = mn0; mrow1 = mn1;

        // ---- y += P V ----
#pragma unroll
        for (int f = 0; f < 8; f++) {
            int dr = 8*f + gid;
#pragma unroll
            for (int kc = 0; kc < 2; kc++) {
                uint32_t vbh[2], vbl[2];
                vbh[0] = Vwh[dr*20 + 8*kc + tg];
                vbh[1] = Vwh[dr*20 + 8*kc + tg + 4];
                vbl[0] = Vwl[dr*20 + 8*kc + tg];
                vbl[1] = Vwl[dr*20 + 8*kc + tg + 4];
                mma_bf16(yacc[f], pl[kc], vbh);
                mma_bf16(yacc[f], ph[kc], vbl);
                mma_bf16(yacc[f], ph[kc], vbh);
            }
        }
    }

    // ---- write y (split planes) ----
    float inv0 = 1.f / lrow0, inv1 = 1.f / lrow1;
#pragma unroll
    for (int f = 0; f < 8; f++) {
        int d = hh*kDH + 8*f + 2*tg;
        if (qrow0 < kTA) {
            long a = ((long)(bb*kTA + qrow0))*kC + d;
            __nv_bfloat16 h0,l0,h1,l1;
            bsplit(yacc[f][0]*inv0, h0, l0); bsplit(yacc[f][1]*inv0, h1, l1);
            *(__nv_bfloat162*)&ys[a] = __nv_bfloat162{h0,h1};
            *(__nv_bfloat162*)&ys[planeN + a] = __nv_bfloat162{l0,l1};
        }
        if (qrow1 < kTA) {
            long a = ((long)(bb*kTA + qrow1))*kC + d;
            __nv_bfloat16 h0,l0,h1,l1;
            bsplit(yacc[f][2]*inv1, h0, l0); bsplit(yacc[f][3]*inv1, h1, l1);
            *(__nv_bfloat162*)&ys[a] = __nv_bfloat162{h0,h1};
            *(__nv_bfloat162*)&ys[planeN + a] = __nv_bfloat162{l0,l1};
        }
    }
}

// ---------------- layernorm (writes split planes) ----------------
__global__ __launch_bounds__(256)
void ln_k(const float* __restrict__ x, const float* __restrict__ w,
          const float* __restrict__ b, __nv_bfloat16* __restrict__ o, long planeN)
{
    const long row = blockIdx.x;
    const float* xr = x + row*kC;
    float s = 0.f, s2 = 0.f;
    for (int c = threadIdx.x; c < kC; c += 256) { float v = xr[c]; s += v; s2 += v*v; }
    __shared__ float sh[64];
#pragma unroll
    for (int off=16;off;off>>=1){ s += __shfl_xor_sync(0xffffffffu,s,off); s2 += __shfl_xor_sync(0xffffffffu,s2,off); }
    int wid = threadIdx.x >> 5, lane = threadIdx.x & 31;
    if (lane == 0){ sh[wid] = s; sh[32+wid] = s2; }
    __syncthreads();
    if (threadIdx.x < 32) {
        s  = (lane < 8) ? sh[lane]    : 0.f;
        s2 = (lane < 8) ? sh[32+lane] : 0.f;
#pragma unroll
        for (int off=4;off;off>>=1){ s += __shfl_xor_sync(0xffffffffu,s,off); s2 += __shfl_xor_sync(0xffffffffu,s2,off); }
        if (lane == 0){ sh[0] = s; sh[1] = s2; }
    }
    __syncthreads();
    float mean = sh[0] * (1.f/kC);
    float var  = sh[1] * (1.f/kC) - mean*mean;
    float rstd = rsqrtf(var + 1e-5f);
    for (int c = threadIdx.x; c < kC; c += 256) {
        float v = (xr[c]-mean)*rstd*w[c] + b[c];
        __nv_bfloat16 h,lo2; bsplit(v,h,lo2);
        o[row*kC + c] = h;
        o[planeN + row*kC + c] = lo2;
    }
}

// ---------------- small kernels ----------------
__global__ void pool_k(const float* __restrict__ mem, __nv_bfloat16* __restrict__ pooled, long planeN)
{
    const int bm = blockIdx.x;
    const int bI = bm / kM, mI = bm % kM;
    const int seg = kT / kM;
    const float* src = mem + ((long)bI*kT + (long)mI*seg)*kC;
    for (int c = threadIdx.x; c < kC; c += blockDim.x) {
        float s = 0.f;
        for (int t = 0; t < seg; t++) s += src[(long)t*kC + c];
        float v = s * (1.f/seg);
        __nv_bfloat16 h,l; bsplit(v,h,l);
        pooled[(long)bm*kC + c] = h;
        pooled[planeN + (long)bm*kC + c] = l;
    }
}

__global__ void concat_k(const float* __restrict__ retr, const float* __restrict__ pm,
                         const float* __restrict__ x, float* __restrict__ xa)
{
    long i = (long)blockIdx.x*blockDim.x + threadIdx.x;
    if (i >= (long)kB*kTA*kC) return;
    int c = (int)(i % kC); long r = i / kC; int t = (int)(r % kTA); int b = (int)(r / kTA);
    float v;
    if (t < kM)        v = retr[((long)b*kM + t)*kC + c];
    else if (t < kPRE) v = pm[(long)(t-kM)*kC + c];
    else               v = x[((long)b*kT + (t-kPRE))*kC + c];
    xa[i] = v;
}

__global__ void copyout_k(const float* __restrict__ xa2, float* __restrict__ out,
                          __nv_bfloat16* __restrict__ outs, long planeN)
{
    long i = (long)blockIdx.x*blockDim.x + threadIdx.x;
    if (i >= OUT_N) return;
    int c = (int)(i % kC); long r = i / kC; int t = (int)(r % kT); int b = (int)(r / kT);
    float v = xa2[((long)b*kTA + kPRE + t)*kC + c];
    out[i] = v;
    __nv_bfloat16 h,l; bsplit(v,h,l);
    outs[i] = h; outs[planeN + i] = l;
}

__global__ void silu_k(const float* __restrict__ z, float* __restrict__ o,
                       __nv_bfloat16* __restrict__ os, long planeN, long n)
{
    long i = (long)blockIdx.x*blockDim.x + threadIdx.x;
    if (i >= n) return;
    float v = z[i];
    float r = v / (1.f + __expf(-v));
    o[i] = r;
    __nv_bfloat16 h,l; bsplit(r,h,l);
    os[i] = h; os[planeN + i] = l;
}

__global__ void dpred_k(float* __restrict__ p, const float* __restrict__ v,
                        __nv_bfloat16* __restrict__ ps, long planeN, long n, float scale)
{
    long i = (long)blockIdx.x*blockDim.x + threadIdx.x;
    if (i >= n) return;
    float r = (p[i] - v[i]) * scale;
    p[i] = r;
    __nv_bfloat16 h,l; bsplit(r,h,l);
    ps[i] = h; ps[planeN + i] = l;
}

__global__ void zero_k(float* __restrict__ a, long n)
{
    long i = (long)blockIdx.x*blockDim.x + threadIdx.x;
    if (i < n) a[i] = 0.f;
}

__global__ void colsum_k(const float* __restrict__ in, float* __restrict__ out,
                         int rows, int cols, int rowsPerSeg)
{
    int z = blockIdx.z;
    in  += (long)z*rows*cols;
    out += (long)z*cols;
    int j = blockIdx.x*blockDim.x + threadIdx.x;
    if (j >= cols) return;
    int t0 = blockIdx.y * rowsPerSeg;
    int t1 = t0 + rowsPerSeg; if (t1 > rows) t1 = rows;
    float s = 0.f;
    for (int t = t0; t < t1; t++) s += in[(long)t*cols + j];
    atomicAdd(out + j, s);
}

__global__ void update_k(const float* __restrict__ w, const float* __restrict__ mom,
                         const float* __restrict__ g, float* __restrict__ outW,
                         float* __restrict__ outM, long n)
{
    long i = (long)blockIdx.x*blockDim.x + threadIdx.x;
    if (i >= n) return;
    float nm = kMU*mom[i] + g[i];
    outM[i] = nm;
    outW[i] = (1.f - kDECAY)*w[i] - kLR*nm;
}

__global__ void split_k(const float* __restrict__ in, __nv_bfloat16* __restrict__ out, long n)
{
    long i = (long)blockIdx.x*blockDim.x + threadIdx.x;
    if (i >= n) return;
    __nv_bfloat16 h,l; bsplit(in[i],h,l);
    out[i] = h; out[n + i] = l;
}

__global__ void transpose_split_k(const float* __restrict__ in, __nv_bfloat16* __restrict__ out,
                                  long planeN, int rows, int cols)
{
    __shared__ float tile[32][33];
    long zoff = (long)blockIdx.z * rows * cols;
    int c0 = blockIdx.x*32, r0 = blockIdx.y*32;
    int tx = threadIdx.x, ty = threadIdx.y;
#pragma unroll
    for (int i = 0; i < 32; i += 8) {
        int r = r0 + ty + i, c = c0 + tx;
        if (r < rows && c < cols) tile[ty+i][tx] = in[zoff + (long)r*cols + c];
    }
    __syncthreads();
#pragma unroll
    for (int i = 0; i < 32; i += 8) {
        int r = c0 + ty + i, c = r0 + tx;
        if (r < cols && c < rows) {
            __nv_bfloat16 h,l; bsplit(tile[tx][ty+i],h,l);
            out[zoff + (long)r*rows + c] = h;
            out[planeN + zoff + (long)r*rows + c] = l;
        }
    }
}

// ---------------- host side ----------------
template<int EPI, bool WF32, bool WSPLIT>
static void bgemm(const __nv_bfloat16* A, long aPlane, long sA,
                  const __nv_bfloat16* B, long bPlane, long sB,
                  const float* bias, long sBias, const float* res, long sRes,
                  float* C, __nv_bfloat16* Cs, long cPlane, long sC,
                  int M, int N, int K, int batch)
{
    cudaFuncSetAttribute(bgemm_k<EPI,WF32,WSPLIT>,
                         cudaFuncAttributeMaxDynamicSharedMemorySize, MSMEM);
    dim3 grid(N/MBN, (M + MBM - 1)/MBM, batch);
    bgemm_k<EPI,WF32,WSPLIT><<<grid, 256, MSMEM>>>(A, B, bias, res, C, Cs,
        M, N, K, aPlane, bPlane, cPlane, sA, sB, sBias, sRes, sC);
}

static inline long cdiv(long a, long b){ return (a + b - 1)/b; }

#define GETF(var, sym) float* var; { void* _p=nullptr; cudaGetSymbolAddress(&_p, sym); var=(float*)_p; }
#define GETB(var, sym) __nv_bfloat16* var; { void* _p=nullptr; cudaGetSymbolAddress(&_p, sym); var=(__nv_bfloat16*)_p; }

extern "C" void kernel_launch(void* const* d_in, const int* in_sizes, int n_in,
                              void* d_out, int out_size)
{
    const float* x       = (const float*)d_in[0];
    const float* persist = (const float*)d_in[1];
    const float* ln1w    = (const float*)d_in[2];
    const float* ln1b    = (const float*)d_in[3];
    const float* ln2w    = (const float*)d_in[4];
    const float* ln2b    = (const float*)d_in[5];
    const float* attnw   = (const float*)d_in[6];
    const float* attnb   = (const float*)d_in[7];
    const float* projw   = (const float*)d_in[8];
    const float* projb   = (const float*)d_in[9];
    const float* fcw     = (const float*)d_in[10];
    const float* fcb     = (const float*)d_in[11];
    const float* mlpw    = (const float*)d_in[12];
    const float* mlpb    = (const float*)d_in[13];
    const float* qw      = (const float*)d_in[14];
    const float* qb      = (const float*)d_in[15];
    const float* kw      = (const float*)d_in[16];
    const float* kb      = (const float*)d_in[17];
    const float* vw      = (const float*)d_in[18];
    const float* vb      = (const float*)d_in[19];
    const float* ow      = (const float*)d_in[20];
    const float* ob      = (const float*)d_in[21];
    const float* memw0   = (const float*)d_in[22];
    const float* memb0   = (const float*)d_in[23];
    const float* memw1   = (const float*)d_in[24];
    const float* memb1   = (const float*)d_in[25];
    const float* momw0   = (const float*)d_in[26];
    const float* momb0   = (const float*)d_in[27];
    const float* momw1   = (const float*)d_in[28];
    const float* momb1   = (const float*)d_in[29];
    float* out = (float*)d_out;

    GETF(zbuf, g_h);    GETF(hh, g_hh);    GETF(memb, g_mem);  GETF(retr, g_retr);
    GETF(xa, g_xa);     GETF(xa2, g_xa2);  GETF(keys, g_keys);
    GETF(vals, g_vals); GETF(dh, g_dh);    GETF(gw0, g_gw0);   GETF(gw1, g_gw1);
    GETF(gb0, g_gb0);   GETF(gb1, g_gb1);

    GETB(px,    s_x);     GETB(pq,    s_q);     GETB(ph,    s_h);     GETB(ppool, s_pool);
    GETB(phln,  s_hln);   GETB(pqkv,  s_qkv);   GETB(py,    s_y);     GETB(phfc,  s_hfc);
    GETB(pout,  s_out);   GETB(pkeys, s_keys);  GETB(phh,   s_hh);    GETB(pdp,   s_dp);
    GETB(pdpT,  s_dpT);   GETB(phhT,  s_hhT);   GETB(pdzT,  s_dzT);   GETB(pkeysT,s_keysT);
    GETB(pw1T,  s_w1T);
    GETB(pqw,   s_qw);    GETB(pkw,   s_kw);    GETB(pvw,   s_vw);    GETB(pow_,  s_ow);
    GETB(pprojw,s_projw); GETB(pattnw,s_attnw); GETB(pfcw,  s_fcw);   GETB(pmlpw, s_mlpw);
    GETB(pw0,   s_w0);    GETB(pw1,   s_w1);

    const long sTC = (long)kT*kC, sTH = (long)kT*kHID;
    const long sW0 = (long)kHID*kC, sW1 = (long)kC*kHID;

    auto split = [&](const float* in, __nv_bfloat16* outp, long n){
        split_k<<<(unsigned)cdiv(n,256),256>>>(in, outp, n);
    };
    split(x, px, N_X);
    split(qw, pqw, N_SQW);   split(kw, pkw, N_SQW);   split(vw, pvw, N_SQW);
    split(ow, pow_, N_SQW);  split(projw, pprojw, N_SQW);
    split(attnw, pattnw, N_ATTNW);
    split(fcw, pfcw, N_FCW); split(mlpw, pmlpw, N_MLPW);
    split(memw0, pw0, N_W0); split(memw1, pw1, N_W1);
    transpose_split_k<<<dim3(kHID/32, kC/32, kB), dim3(32,8)>>>(memw1, pw1T, N_W1T, kC, kHID);

    // --- forward memory read path ---
    bgemm<EP_NONE,false,true>(px,N_X,0, pqw,N_SQW,0, qb,0, nullptr,0,
                              nullptr, pq,N_Q, 0, kB*kT, kC, kC, 1);
    bgemm<EP_SILU,false,true>(pq,N_Q,sTC, pw0,N_W0,sW0, memb0,kHID, nullptr,0,
                              nullptr, ph,N_H, sTH, kT, kHID, kC, kB);
    bgemm<EP_NONE,true,false>(ph,N_H,sTH, pw1,N_W1,sW1, memb1,kC, nullptr,0,
                              memb, nullptr,0, sTC, kT, kC, kHID, kB);
    pool_k<<<kB*kM, 256>>>(memb, ppool, N_POOL);
    bgemm<EP_NONE,true,false>(ppool,N_POOL,0, pow_,N_SQW,0, ob,0, nullptr,0,
                              retr, nullptr,0, 0, kB*kM, kC, kC, 1);
    {
        long n = (long)kB*kTA*kC;
        concat_k<<<(unsigned)cdiv(n,256),256>>>(retr, persist, x, xa);
    }

    // --- transformer block ---
    ln_k<<<kB*kTA,256>>>(xa, ln1w, ln1b, phln, N_HLN);
    bgemm<EP_NONE,false,true>(phln,N_HLN,0, pattnw,N_ATTNW,0, attnb,0, nullptr,0,
                              nullptr, pqkv,N_QKV, 0, kB*kTA, 3*kC, kC, 1);
    attn_mma_k<<<dim3((kTA+63)/64, kB*kH), 128>>>(pqkv, N_QKV, py, N_Y);
    bgemm<EP_NONE,true,false>(py,N_Y,0, pprojw,N_SQW,0, projb,0, xa,0,
                              xa2, nullptr,0, 0, kB*kTA, kC, kC, 1);
    ln_k<<<kB*kTA,256>>>(xa2, ln2w, ln2b, phln, N_HLN);
    bgemm<EP_GELU,false,true>(phln,N_HLN,0, pfcw,N_FCW,0, fcb,0, nullptr,0,
                              nullptr, phfc,N_HFC, 0, kB*kTA, 4*kC, kC, 1);
    bgemm<EP_NONE,true,false>(phfc,N_HFC,0, pmlpw,N_MLPW,0, mlpb,0, xa2,0,
                              xa2, nullptr,0, 0, kB*kTA, kC, 4*kC, 1);
    copyout_k<<<(unsigned)cdiv(OUT_N,256),256>>>(xa2, out, pout, N_OUT);

    // --- memory write path ---
    bgemm<EP_NONE,true,true>(pout,N_OUT,0, pkw,N_SQW,0, kb,0, nullptr,0,
                             keys, pkeys,N_KEYS, 0, kB*kT, kC, kC, 1);
    bgemm<EP_NONE,true,false>(pout,N_OUT,0, pvw,N_SQW,0, vb,0, nullptr,0,
                              vals, nullptr,0, 0, kB*kT, kC, kC, 1);
    bgemm<EP_NONE,true,false>(pkeys,N_KEYS,sTC, pw0,N_W0,sW0, memb0,kHID, nullptr,0,
                              zbuf, nullptr,0, sTH, kT, kHID, kC, kB);
    {
        long n = (long)kB*kT*kHID;
        silu_k<<<(unsigned)cdiv(n,256),256>>>(zbuf, hh, phh, N_HH, n);
    }
    bgemm<EP_NONE,true,false>(phh,N_HH,sTH, pw1,N_W1,sW1, memb1,kC, nullptr,0,
                              memb, nullptr,0, sTC, kT, kC, kHID, kB);
    {
        long n = (long)kB*kT*kC;
        dpred_k<<<(unsigned)cdiv(n,256),256>>>(memb, vals, pdp, N_DP, n, 2.f/((float)kT*(float)kC));
    }
    zero_k<<<(unsigned)cdiv(B0_N,256),256>>>(gb0, B0_N);
    zero_k<<<(unsigned)cdiv(B1_N,256),256>>>(gb1, B1_N);
    colsum_k<<<dim3((kC+255)/256, 8, kB),256>>>(memb, gb1, kT, kC, kT/8);

    transpose_split_k<<<dim3(kC/32,  kT/32, kB), dim3(32,8)>>>(memb, pdpT, N_DPT, kT, kC);
    transpose_split_k<<<dim3(kHID/32,kT/32, kB), dim3(32,8)>>>(hh,   phhT, N_HHT, kT, kHID);

    bgemm<EP_NONE,true,false>(pdpT,N_DPT,sTC, phhT,N_HHT,sTH, nullptr,0, nullptr,0,
                              gw1, nullptr,0, sW1, kC, kHID, kT, kB);
    // dh = dpred @ w1, fused with dsilu'(z)
    bgemm<EP_DSILU,true,false>(pdp,N_DP,sTC, pw1T,N_W1T,sW0, nullptr,0, zbuf,sTH,
                               dh, nullptr,0, sTH, kT, kHID, kC, kB);
    colsum_k<<<dim3((kHID+255)/256, 8, kB),256>>>(dh, gb0, kT, kHID, kT/8);
    transpose_split_k<<<dim3(kHID/32,kT/32, kB), dim3(32,8)>>>(dh,   pdzT,  N_DZT,  kT, kHID);
    transpose_split_k<<<dim3(kC/32,  kT/32, kB), dim3(32,8)>>>(keys, pkeysT,N_KEYST,kT, kC);
    bgemm<EP_NONE,true,false>(pdzT,N_DZT,sTH, pkeysT,N_KEYST,sTC, nullptr,0, nullptr,0,
                              gw0, nullptr,0, sW0, kHID, kC, kT, kB);

    // --- updates into output tuple ---
    update_k<<<(unsigned)cdiv(W0_N,256),256>>>(memw0, momw0, gw0, out+OFF_NW0, out+OFF_NMW0, W0_N);
    update_k<<<(unsigned)cdiv(B0_N,256),256>>>(memb0, momb0, gb0, out+OFF_NB0, out+OFF_NMB0, B0_N);
    update_k<<<(unsigned)cdiv(W1_N,256),256>>>(memw1, momw1, gw1, out+OFF_NW1, out+OFF_NMW1, W1_N);
    update_k<<<(unsigned)cdiv(B1_N,256),256>>>(memb1, momb1, gb1, out+OFF_NB1, out+OFF_NMB1, B1_N);

    (void)in_sizes; (void)n_in; (void)out_size;
}